// round 6
// baseline (speedup 1.0000x reference)
#include <cuda_runtime.h>
#include <cuda_bf16.h>
#include <cstdint>

#define BATCH 8
#define CH    256
#define KDIM  512
#define KP    256      // KDIM/2 packed bf16 pairs
#define VHW   1024     // 32*32
#define H_OUT 128
#define W_OUT 128
#define HWOUT (H_OUT * W_OUT)

// v scratch (8 MiB, L2-resident between kernels)
__device__ float g_v[BATCH * CH * VHW];
// bf16-split packed operands (pairs along k)
__device__ unsigned g_Wh[CH * KP];
__device__ unsigned g_Wl[CH * KP];
__device__ unsigned g_Xh[BATCH * KP * VHW];
__device__ unsigned g_Xl[BATCH * KP * VHW];
// cossim partials: [s(3)][chunk(8)][b(8)][pix] = 12.6 MB
#define NCHUNK 8
__device__ float g_part[3 * NCHUNK * BATCH * HWOUT];

// ---------------------------------------------------------------------------
// bf16 split helpers
// ---------------------------------------------------------------------------
__device__ __forceinline__ void split1(float x, unsigned short& h, unsigned short& l) {
    __nv_bfloat16 hb = __float2bfloat16(x);
    float r = x - __bfloat162float(hb);
    __nv_bfloat16 lb = __float2bfloat16(r);
    h = __bfloat16_as_ushort(hb);
    l = __bfloat16_as_ushort(lb);
}
__device__ __forceinline__ void pack2(float a, float b, unsigned& hi, unsigned& lo) {
    unsigned short h0, l0, h1, l1;
    split1(a, h0, l0);
    split1(b, h1, l1);
    hi = (unsigned)h0 | ((unsigned)h1 << 16);
    lo = (unsigned)l0 | ((unsigned)l1 << 16);
}

__device__ __forceinline__ void mma_bf16(float* d, const unsigned* a, unsigned b0, unsigned b1) {
    asm volatile(
        "mma.sync.aligned.m16n8k16.row.col.f32.bf16.bf16.f32 "
        "{%0,%1,%2,%3}, {%4,%5,%6,%7}, {%8,%9}, {%0,%1,%2,%3};"
        : "+f"(d[0]), "+f"(d[1]), "+f"(d[2]), "+f"(d[3])
        : "r"(a[0]), "r"(a[1]), "r"(a[2]), "r"(a[3]), "r"(b0), "r"(b1));
}

// ---------------------------------------------------------------------------
// Pre-split converter (validated in R3): fp32 -> packed bf16 hi/lo k-pairs.
// ---------------------------------------------------------------------------
__global__ __launch_bounds__(256)
void convert_kernel(const float* __restrict__ xvit, const float* __restrict__ Wmat) {
    const int gid = blockIdx.x * 256 + threadIdx.x;   // 524288 total
    const int n4 = gid & 255;
    const int kp = (gid >> 8) & 255;
    const int b  = gid >> 16;

    {   // X: rows 2kp, 2kp+1, 4 columns
        const float* xs = xvit + ((size_t)(b * KDIM + 2 * kp) * VHW) + n4 * 4;
        float4 r0 = *(const float4*)xs;
        float4 r1 = *(const float4*)(xs + VHW);
        uint4 hi, lo;
        pack2(r0.x, r1.x, hi.x, lo.x);
        pack2(r0.y, r1.y, hi.y, lo.y);
        pack2(r0.z, r1.z, hi.z, lo.z);
        pack2(r0.w, r1.w, hi.w, lo.w);
        size_t o = ((size_t)(b * KP + kp) * VHW) + n4 * 4;
        *(uint4*)&g_Xh[o] = hi;
        *(uint4*)&g_Xl[o] = lo;
    }
    if (gid < CH * 64) {   // W: m = gid>>6, kp-quad = gid&63
        const int m = gid >> 6;
        const int kq = gid & 63;
        const float* ws = Wmat + (size_t)m * KDIM + kq * 8;
        float4 r0 = *(const float4*)ws;
        float4 r1 = *(const float4*)(ws + 4);
        uint4 hi, lo;
        pack2(r0.x, r0.y, hi.x, lo.x);
        pack2(r0.z, r0.w, hi.y, lo.y);
        pack2(r1.x, r1.y, hi.z, lo.z);
        pack2(r1.z, r1.w, hi.w, lo.w);
        size_t o = (size_t)m * KP + kq * 4;
        *(uint4*)&g_Wh[o] = hi;
        *(uint4*)&g_Wl[o] = lo;
    }
}

// ---------------------------------------------------------------------------
// Tensor-core GEMM from pre-split bf16: BM=64, BN=64, 128 thr (4 warps,
// 32x32 warp tiles), double-buffered smem, ONE sync per 32-k window.
// C ≈ Wh*Xh + Wh*Xl + Wl*Xh accumulated in one k-loop.
// ---------------------------------------------------------------------------
#define AS_STR 20
#define XS_STR 72

__global__ __launch_bounds__(128)
void gemm_mma_kernel(const float* __restrict__ bias) {
    const int n0 = blockIdx.x * 64;
    const int m0 = blockIdx.y * 64;
    const int bb = blockIdx.z;

    __shared__ unsigned Ash[2][64 * AS_STR];
    __shared__ unsigned Asl[2][64 * AS_STR];
    __shared__ unsigned Xsh[2][16 * XS_STR];
    __shared__ unsigned Xsl[2][16 * XS_STR];

    const int tid  = threadIdx.x;
    const int wid  = tid >> 5;
    const int lane = tid & 31;
    const int g    = lane >> 2;
    const int t4   = lane & 3;
    const int warp_m = (wid >> 1) * 32;
    const int warp_n = (wid & 1) * 32;

    // staging indices
    const int arow = tid >> 1, ahalf = tid & 1;       // A: 64 rows x 2 halves(8kp)
    const int xrow = tid >> 3, xc8 = (tid & 7) * 8;   // X: 16 kp-rows x 8-n chunks

    const unsigned* wph = g_Wh + (size_t)(m0 + arow) * KP + ahalf * 8;
    const unsigned* wpl = g_Wl + (size_t)(m0 + arow) * KP + ahalf * 8;
    const unsigned* xph = g_Xh + ((size_t)bb * KP + xrow) * VHW + n0 + xc8;
    const unsigned* xpl = g_Xl + ((size_t)bb * KP + xrow) * VHW + n0 + xc8;

    uint4 rwh0, rwh1, rwl0, rwl1, rxh0, rxh1, rxl0, rxl1;

    #define LOADW(tw) do { \
        const int kw_ = (tw) * 16; \
        rwh0 = *(const uint4*)(wph + kw_);               \
        rwh1 = *(const uint4*)(wph + kw_ + 4);           \
        rwl0 = *(const uint4*)(wpl + kw_);               \
        rwl1 = *(const uint4*)(wpl + kw_ + 4);           \
        rxh0 = *(const uint4*)(xph + (size_t)kw_ * VHW);     \
        rxh1 = *(const uint4*)(xph + (size_t)kw_ * VHW + 4); \
        rxl0 = *(const uint4*)(xpl + (size_t)kw_ * VHW);     \
        rxl1 = *(const uint4*)(xpl + (size_t)kw_ * VHW + 4); \
    } while (0)

    #define STSW(bf) do { \
        unsigned* dah = &Ash[bf][arow * AS_STR + ahalf * 8]; \
        unsigned* dal = &Asl[bf][arow * AS_STR + ahalf * 8]; \
        *(uint4*)dah = rwh0; *(uint4*)(dah + 4) = rwh1;      \
        *(uint4*)dal = rwl0; *(uint4*)(dal + 4) = rwl1;      \
        unsigned* dxh = &Xsh[bf][xrow * XS_STR + xc8];       \
        unsigned* dxl = &Xsl[bf][xrow * XS_STR + xc8];       \
        *(uint4*)dxh = rxh0; *(uint4*)(dxh + 4) = rxh1;      \
        *(uint4*)dxl = rxl0; *(uint4*)(dxl + 4) = rxl1;      \
    } while (0)

    float acc[2][4][4];
    #pragma unroll
    for (int i = 0; i < 2; i++)
        #pragma unroll
        for (int j = 0; j < 4; j++)
            #pragma unroll
            for (int q = 0; q < 4; q++) acc[i][j][q] = 0.f;

    const int NT = KP / 16;   // 16 windows of 32 k
    LOADW(0);
    STSW(0);
    LOADW(1);
    __syncthreads();

    int buf = 0;
    for (int tw = 0; tw < NT; tw++) {
        if (tw < NT - 1) {
            STSW(buf ^ 1);
            if (tw < NT - 2) LOADW(tw + 2);
        }
        #pragma unroll
        for (int kb = 0; kb < 2; kb++) {
            unsigned ah[2][4], al[2][4];
            #pragma unroll
            for (int mt = 0; mt < 2; mt++) {
                const int ab = (warp_m + mt * 16 + g) * AS_STR + kb * 8 + t4;
                ah[mt][0] = Ash[buf][ab];
                ah[mt][1] = Ash[buf][ab + 8 * AS_STR];
                ah[mt][2] = Ash[buf][ab + 4];
                ah[mt][3] = Ash[buf][ab + 8 * AS_STR + 4];
                al[mt][0] = Asl[buf][ab];
                al[mt][1] = Asl[buf][ab + 8 * AS_STR];
                al[mt][2] = Asl[buf][ab + 4];
                al[mt][3] = Asl[buf][ab + 8 * AS_STR + 4];
            }
            #pragma unroll
            for (int nt = 0; nt < 4; nt++) {
                const int xb = (kb * 8 + t4) * XS_STR + warp_n + nt * 8 + g;
                unsigned bh0 = Xsh[buf][xb];
                unsigned bh1 = Xsh[buf][xb + 4 * XS_STR];
                unsigned bl0 = Xsl[buf][xb];
                unsigned bl1 = Xsl[buf][xb + 4 * XS_STR];
                #pragma unroll
                for (int mt = 0; mt < 2; mt++) {
                    mma_bf16(acc[mt][nt], ah[mt], bh0, bh1);  // hh
                    mma_bf16(acc[mt][nt], ah[mt], bl0, bl1);  // hl
                    mma_bf16(acc[mt][nt], al[mt], bh0, bh1);  // lh
                }
            }
        }
        __syncthreads();
        buf ^= 1;
    }

    // epilogue
    float* Cg = g_v + (size_t)bb * CH * VHW;
    #pragma unroll
    for (int mt = 0; mt < 2; mt++) {
        const int r0 = m0 + warp_m + mt * 16 + g;
        const float bv0 = bias[r0];
        const float bv1 = bias[r0 + 8];
        #pragma unroll
        for (int nt = 0; nt < 4; nt++) {
            const int c = n0 + warp_n + nt * 8 + 2 * t4;
            *(float2*)&Cg[(size_t)r0 * VHW + c] =
                make_float2(acc[mt][nt][0] + bv0, acc[mt][nt][1] + bv0);
            *(float2*)&Cg[(size_t)(r0 + 8) * VHW + c] =
                make_float2(acc[mt][nt][2] + bv1, acc[mt][nt][3] + bv1);
        }
    }
}

// ---------------------------------------------------------------------------
// Phase 1: fused bilinear + partial cossim, 8 px/thread.
// Tile 128(w) x 8(h); warp wrp handles fine rows y and y+4 (same fy, shared
// middle coarse row -> 9 LDS serve both rows). grid (8, 16, 8) = 1024 blocks.
// ---------------------------------------------------------------------------
#define CB_CCH   32
#define CB_ELEMS 136   // 4 rows * 34 cols

__global__ __launch_bounds__(128)
void cossim_part_kernel(const float* __restrict__ xcnn) {
    const int cc   = blockIdx.x;
    const int by   = blockIdx.y;          // fine rows by*8 .. by*8+7
    const int bb   = blockIdx.z;
    const int lane = threadIdx.x & 31;
    const int wrp  = threadIdx.x >> 5;
    const int y1   = by * 8 + wrp;        // second row: y1 + 4
    const int x0   = lane * 4;
    const int c0   = cc * CB_CCH;

    __shared__ float vsf[CB_CCH * CB_ELEMS];   // 17.4 KB

    // staging offsets (coarse rows 2by-1 .. 2by+2, cols -1..32, clamped)
    int gsrc[5];
    #pragma unroll
    for (int e = 0; e < 5; e++) {
        int idx = lane + 32 * e;
        int row = idx / 34;
        int col = idx - row * 34;
        int gy = min(max(2 * by - 1 + row, 0), 31);
        int gx = min(max(col - 1, 0), 31);
        gsrc[e] = gy * 32 + gx;
    }
    const bool v4 = lane < (CB_ELEMS - 128);   // lane < 8

    const float fy = (wrp == 0) ? 0.625f : (wrp == 1) ? 0.875f
                   : (wrp == 2) ? 0.125f : 0.375f;
    const int rb = ((wrp >= 2) ? 34 : 0) + lane;   // top row offset + column

    const float* vbase = g_v + (size_t)bb * CH * VHW;
    for (int c = wrp; c < CB_CCH; c += 4) {
        const float* vc = vbase + (size_t)(c0 + c) * VHW;
        float t0 = vc[gsrc[0]];
        float t1 = vc[gsrc[1]];
        float t2 = vc[gsrc[2]];
        float t3 = vc[gsrc[3]];
        float* d = &vsf[c * CB_ELEMS + lane];
        d[0] = t0; d[32] = t1; d[64] = t2; d[96] = t3;
        if (v4) d[128] = vc[gsrc[4]];
    }
    __syncthreads();

    float dA0=0.f,dA1=0.f,dA2=0.f,dA3=0.f, cA0=0.f,cA1=0.f,cA2=0.f,cA3=0.f,
          vA0=0.f,vA1=0.f,vA2=0.f,vA3=0.f;
    float dB0=0.f,dB1=0.f,dB2=0.f,dB3=0.f, cB0=0.f,cB1=0.f,cB2=0.f,cB3=0.f,
          vB0=0.f,vB1=0.f,vB2=0.f,vB3=0.f;

    const float* xc1 = xcnn + (size_t)(bb * CH + c0) * HWOUT + (size_t)y1 * W_OUT + x0;

    #pragma unroll 8
    for (int c = 0; c < CB_CCH; c++) {
        float4 xa = *(const float4*)(xc1 + (size_t)c * HWOUT);
        float4 xb = *(const float4*)(xc1 + (size_t)c * HWOUT + 4 * W_OUT);
        const float* vp = &vsf[c * CB_ELEMS + rb];
        float a0 = vp[0],  a1 = vp[1],  a2 = vp[2];
        float m0 = vp[34], m1 = vp[35], m2 = vp[36];
        float q0 = vp[68], q1 = vp[69], q2 = vp[70];
        // vertical lerps (rows y1: a->m; y1+4: m->q; same fy)
        float cvA0 = fmaf(fy, m0 - a0, a0);
        float cvA1 = fmaf(fy, m1 - a1, a1);
        float cvA2 = fmaf(fy, m2 - a2, a2);
        float cvB0 = fmaf(fy, q0 - m0, m0);
        float cvB1 = fmaf(fy, q1 - m1, m1);
        float cvB2 = fmaf(fy, q2 - m2, m2);
        // horizontal
        float dA01 = cvA1 - cvA0, dA12 = cvA2 - cvA1;
        float dB01 = cvB1 - cvB0, dB12 = cvB2 - cvB1;
        float uA0 = fmaf(0.625f, dA01, cvA0);
        float uA1 = fmaf(0.875f, dA01, cvA0);
        float uA2 = fmaf(0.125f, dA12, cvA1);
        float uA3 = fmaf(0.375f, dA12, cvA1);
        float uB0 = fmaf(0.625f, dB01, cvB0);
        float uB1 = fmaf(0.875f, dB01, cvB0);
        float uB2 = fmaf(0.125f, dB12, cvB1);
        float uB3 = fmaf(0.375f, dB12, cvB1);
        dA0 = fmaf(xa.x, uA0, dA0); cA0 = fmaf(xa.x, xa.x, cA0); vA0 = fmaf(uA0, uA0, vA0);
        dA1 = fmaf(xa.y, uA1, dA1); cA1 = fmaf(xa.y, xa.y, cA1); vA1 = fmaf(uA1, uA1, vA1);
        dA2 = fmaf(xa.z, uA2, dA2); cA2 = fmaf(xa.z, xa.z, cA2); vA2 = fmaf(uA2, uA2, vA2);
        dA3 = fmaf(xa.w, uA3, dA3); cA3 = fmaf(xa.w, xa.w, cA3); vA3 = fmaf(uA3, uA3, vA3);
        dB0 = fmaf(xb.x, uB0, dB0); cB0 = fmaf(xb.x, xb.x, cB0); vB0 = fmaf(uB0, uB0, vB0);
        dB1 = fmaf(xb.y, uB1, dB1); cB1 = fmaf(xb.y, xb.y, cB1); vB1 = fmaf(uB1, uB1, vB1);
        dB2 = fmaf(xb.z, uB2, dB2); cB2 = fmaf(xb.z, xb.z, cB2); vB2 = fmaf(uB2, uB2, vB2);
        dB3 = fmaf(xb.w, uB3, dB3); cB3 = fmaf(xb.w, xb.w, cB3); vB3 = fmaf(uB3, uB3, vB3);
    }

    const size_t pix1 = (size_t)y1 * W_OUT + x0;
    float* p = g_part + ((size_t)(cc * BATCH + bb)) * HWOUT + pix1;
    const size_t sstr = (size_t)NCHUNK * BATCH * HWOUT;
    *(float4*)(p)                       = make_float4(dA0, dA1, dA2, dA3);
    *(float4*)(p + sstr)                = make_float4(cA0, cA1, cA2, cA3);
    *(float4*)(p + 2 * sstr)            = make_float4(vA0, vA1, vA2, vA3);
    *(float4*)(p + 4 * W_OUT)           = make_float4(dB0, dB1, dB2, dB3);
    *(float4*)(p + 4 * W_OUT + sstr)    = make_float4(cB0, cB1, cB2, cB3);
    *(float4*)(p + 4 * W_OUT + 2 * sstr)= make_float4(vB0, vB1, vB2, vB3);
}

// ---------------------------------------------------------------------------
// Phase 2: reduce 8 chunk-partials -> cosine similarity. 4 px/thread.
// ---------------------------------------------------------------------------
__global__ __launch_bounds__(256)
void cossim_reduce_kernel(float* __restrict__ out) {
    const int gid = blockIdx.x * 256 + threadIdx.x;
    const size_t pix4 = (size_t)gid * 4;
    const int bb  = (int)(pix4 >> 14);
    const size_t pix = pix4 & (HWOUT - 1);
    const size_t sstr = (size_t)NCHUNK * BATCH * HWOUT;
    const float* p = g_part + (size_t)bb * HWOUT + pix;
    const size_t cstr = (size_t)BATCH * HWOUT;

    float4 dot = make_float4(0.f, 0.f, 0.f, 0.f);
    float4 sc  = dot, sv = dot;
    #pragma unroll
    for (int cc = 0; cc < NCHUNK; cc++) {
        float4 d = *(const float4*)(p + cc * cstr);
        float4 a = *(const float4*)(p + cc * cstr + sstr);
        float4 b = *(const float4*)(p + cc * cstr + 2 * sstr);
        dot.x += d.x; dot.y += d.y; dot.z += d.z; dot.w += d.w;
        sc.x  += a.x; sc.y  += a.y; sc.z  += a.z; sc.w  += a.w;
        sv.x  += b.x; sv.y  += b.y; sv.z  += b.z; sv.w  += b.w;
    }
    float4 o;
    o.x = dot.x / (sqrtf(sc.x) * sqrtf(sv.x) + 1e-8f);
    o.y = dot.y / (sqrtf(sc.y) * sqrtf(sv.y) + 1e-8f);
    o.z = dot.z / (sqrtf(sc.z) * sqrtf(sv.z) + 1e-8f);
    o.w = dot.w / (sqrtf(sc.w) * sqrtf(sv.w) + 1e-8f);
    *(float4*)&out[pix4] = o;
}

// ---------------------------------------------------------------------------
extern "C" void kernel_launch(void* const* d_in, const int* in_sizes, int n_in,
                              void* d_out, int out_size) {
    const float* x_cnn = (const float*)d_in[0];   // [8,256,128,128]
    const float* x_vit = (const float*)d_in[1];   // [8,512,32,32]
    const float* Wmat  = (const float*)d_in[2];   // [256,512]
    const float* bias  = (const float*)d_in[3];   // [256]
    float* out = (float*)d_out;                   // [8,1,128,128]

    convert_kernel<<<2048, 256>>>(x_vit, Wmat);
    gemm_mma_kernel<<<dim3(VHW / 64, CH / 64, BATCH), 128>>>(bias);
    cossim_part_kernel<<<dim3(NCHUNK, H_OUT / 8, BATCH), 128>>>(x_cnn);
    cossim_reduce_kernel<<<dim3(BATCH * HWOUT / 4 / 256), 256>>>(out);
}

// round 8
// speedup vs baseline: 1.2180x; 1.2180x over previous
#include <cuda_runtime.h>
#include <cuda_bf16.h>
#include <cstdint>

#define BATCH 8
#define CH    256
#define KDIM  512
#define KP    256      // KDIM/2 packed bf16 pairs
#define VHW   1024     // 32*32
#define H_OUT 128
#define W_OUT 128
#define HWOUT (H_OUT * W_OUT)

// v scratch (8 MiB, L2-resident between kernels)
__device__ float g_v[BATCH * CH * VHW];
// cossim partials: [s(3)][chunk(4)][b(8)][pix] = 6.3 MB
#define NCHUNK 4
__device__ float g_part[3 * NCHUNK * BATCH * HWOUT];

// ---------------------------------------------------------------------------
// bf16 split + mma helpers
// ---------------------------------------------------------------------------
__device__ __forceinline__ void pack2(float a, float b, unsigned& hi, unsigned& lo) {
    __nv_bfloat16 ha = __float2bfloat16(a);
    __nv_bfloat16 hb = __float2bfloat16(b);
    __nv_bfloat16 la = __float2bfloat16(a - __bfloat162float(ha));
    __nv_bfloat16 lb = __float2bfloat16(b - __bfloat162float(hb));
    hi = (unsigned)__bfloat16_as_ushort(ha) | ((unsigned)__bfloat16_as_ushort(hb) << 16);
    lo = (unsigned)__bfloat16_as_ushort(la) | ((unsigned)__bfloat16_as_ushort(lb) << 16);
}

__device__ __forceinline__ void mma_bf16(float* d, const unsigned* a, unsigned b0, unsigned b1) {
    asm volatile(
        "mma.sync.aligned.m16n8k16.row.col.f32.bf16.bf16.f32 "
        "{%0,%1,%2,%3}, {%4,%5,%6,%7}, {%8,%9}, {%0,%1,%2,%3};"
        : "+f"(d[0]), "+f"(d[1]), "+f"(d[2]), "+f"(d[3])
        : "r"(a[0]), "r"(a[1]), "r"(a[2]), "r"(a[3]), "r"(b0), "r"(b1));
}

__device__ __forceinline__ void ldsm_x4(unsigned* r, unsigned saddr) {
    asm volatile(
        "ldmatrix.sync.aligned.m8n8.x4.shared.b16 {%0,%1,%2,%3}, [%4];"
        : "=r"(r[0]), "=r"(r[1]), "=r"(r[2]), "=r"(r[3]) : "r"(saddr));
}

// ---------------------------------------------------------------------------
// Fused convert + tensor-core GEMM: C[256,1024] = W @ X + bias per batch.
// bf16-split (hh + hl + lh) in one k-loop, fp32 reg-prefetch -> split -> STS.
// BM=128, BN=64, 256 thr, 8 warps = 4m x 2n (32x32 warp tiles), grid 256.
// A fragments via ldmatrix.x4 (conflict-free at AS_STR=20).
// ---------------------------------------------------------------------------
#define AS_STR 20     // ldsm rows: (m*20)%32 in {0,20,8,28,16,4,24,12} -> disjoint 16B groups
#define XS_STR 72     // X frag banks (t*72+g) -> (8t+g) distinct mod 32

__global__ __launch_bounds__(256)
void gemm_fused_kernel(const float* __restrict__ xvit,
                       const float* __restrict__ Wmat,
                       const float* __restrict__ bias) {
    const int n0 = blockIdx.x * 64;
    const int m0 = blockIdx.y * 128;
    const int bb = blockIdx.z;

    __shared__ unsigned Ash[128 * AS_STR];
    __shared__ unsigned Asl[128 * AS_STR];
    __shared__ unsigned Xsh[16 * XS_STR];
    __shared__ unsigned Xsl[16 * XS_STR];

    const int tid  = threadIdx.x;
    const int wid  = tid >> 5;
    const int lane = tid & 31;
    const int g    = lane >> 2;
    const int t4   = lane & 3;
    const int warp_m = (wid >> 1) * 32;   // 0/32/64/96
    const int warp_n = (wid & 1) * 32;    // 0/32

    // ldmatrix per-lane address components (A)
    const int lrow = (lane & 7) + ((lane >> 3) & 1) * 8;   // 0..15
    const int lcol = (lane >> 4) * 4;                      // 0 or 4
    const unsigned ash_u32 = (unsigned)__cvta_generic_to_shared(Ash);
    const unsigned asl_u32 = (unsigned)__cvta_generic_to_shared(Asl);

    // staging indices
    const int arow = tid >> 1, ahalf = tid & 1;       // A: 128 rows x 2 k-halves(16)
    const int xrow = tid >> 4, xc4 = (tid & 15) * 4;  // X: 16 kp-rows x 4-n chunks

    const float* wp = Wmat + (size_t)(m0 + arow) * KDIM + ahalf * 16;
    const float* xp = xvit + ((size_t)bb * KDIM + 2 * xrow) * VHW + n0 + xc4;

    float4 wa[4];   // 16 k of W
    float4 xa[2];   // rows 2kp, 2kp+1 x 4 n

    #pragma unroll
    for (int q = 0; q < 4; q++) wa[q] = *(const float4*)(wp + 4 * q);
    xa[0] = *(const float4*)(xp);
    xa[1] = *(const float4*)(xp + VHW);

    float acc[2][4][4];
    #pragma unroll
    for (int i = 0; i < 2; i++)
        #pragma unroll
        for (int j = 0; j < 4; j++)
            #pragma unroll
            for (int q = 0; q < 4; q++) acc[i][j][q] = 0.f;

    const int NT = KP / 16;   // 16 windows of 32 k
    for (int tw = 0; tw < NT; tw++) {
        {   // A: split + STS
            uint4 h0, l0, h1, l1;
            pack2(wa[0].x, wa[0].y, h0.x, l0.x);
            pack2(wa[0].z, wa[0].w, h0.y, l0.y);
            pack2(wa[1].x, wa[1].y, h0.z, l0.z);
            pack2(wa[1].z, wa[1].w, h0.w, l0.w);
            pack2(wa[2].x, wa[2].y, h1.x, l1.x);
            pack2(wa[2].z, wa[2].w, h1.y, l1.y);
            pack2(wa[3].x, wa[3].y, h1.z, l1.z);
            pack2(wa[3].z, wa[3].w, h1.w, l1.w);
            unsigned* dh = &Ash[arow * AS_STR + ahalf * 8];
            unsigned* dl = &Asl[arow * AS_STR + ahalf * 8];
            *(uint4*)dh = h0; *(uint4*)(dh + 4) = h1;
            *(uint4*)dl = l0; *(uint4*)(dl + 4) = l1;
        }
        {   // X: split + STS (k-pair rows packed)
            uint4 h, l;
            pack2(xa[0].x, xa[1].x, h.x, l.x);
            pack2(xa[0].y, xa[1].y, h.y, l.y);
            pack2(xa[0].z, xa[1].z, h.z, l.z);
            pack2(xa[0].w, xa[1].w, h.w, l.w);
            *(uint4*)&Xsh[xrow * XS_STR + xc4] = h;
            *(uint4*)&Xsl[xrow * XS_STR + xc4] = l;
        }
        __syncthreads();

        if (tw < NT - 1) {   // prefetch next window (overlaps MMA)
            const float* wpn = wp + (tw + 1) * 32;
            const float* xpn = xp + (size_t)(tw + 1) * 32 * VHW;
            #pragma unroll
            for (int q = 0; q < 4; q++) wa[q] = *(const float4*)(wpn + 4 * q);
            xa[0] = *(const float4*)(xpn);
            xa[1] = *(const float4*)(xpn + VHW);
        }

        #pragma unroll
        for (int kb = 0; kb < 2; kb++) {
            unsigned ah[2][4], al[2][4];
            #pragma unroll
            for (int mt = 0; mt < 2; mt++) {
                const unsigned off =
                    (unsigned)(((warp_m + mt * 16 + lrow) * AS_STR + kb * 8 + lcol) * 4);
                ldsm_x4(ah[mt], ash_u32 + off);
                ldsm_x4(al[mt], asl_u32 + off);
            }
            #pragma unroll
            for (int nt = 0; nt < 4; nt++) {
                const int xb = (kb * 8 + t4) * XS_STR + warp_n + nt * 8 + g;
                unsigned bh0 = Xsh[xb];
                unsigned bh1 = Xsh[xb + 4 * XS_STR];
                unsigned bl0 = Xsl[xb];
                unsigned bl1 = Xsl[xb + 4 * XS_STR];
                #pragma unroll
                for (int mt = 0; mt < 2; mt++) {
                    mma_bf16(acc[mt][nt], ah[mt], bh0, bh1);  // hh
                    mma_bf16(acc[mt][nt], ah[mt], bl0, bl1);  // hl
                    mma_bf16(acc[mt][nt], al[mt], bh0, bh1);  // lh
                }
            }
        }
        __syncthreads();
    }

    // epilogue
    float* Cg = g_v + (size_t)bb * CH * VHW;
    #pragma unroll
    for (int mt = 0; mt < 2; mt++) {
        const int r0 = m0 + warp_m + mt * 16 + g;
        const float bv0 = bias[r0];
        const float bv1 = bias[r0 + 8];
        #pragma unroll
        for (int nt = 0; nt < 4; nt++) {
            const int c = n0 + warp_n + nt * 8 + 2 * t4;
            *(float2*)&Cg[(size_t)r0 * VHW + c] =
                make_float2(acc[mt][nt][0] + bv0, acc[mt][nt][1] + bv0);
            *(float2*)&Cg[(size_t)(r0 + 8) * VHW + c] =
                make_float2(acc[mt][nt][2] + bv1, acc[mt][nt][3] + bv1);
        }
    }
}

// ---------------------------------------------------------------------------
// Phase 1: fused bilinear + partial cossim over a 64-channel chunk.
// grid (4, 32, 8) = 1024 blocks, 128 thr; 128(w)x4(h) tile, 4 px/thread.
// (R4-validated body, CB_CCH=64.)
// ---------------------------------------------------------------------------
#define CB_CCH   64
#define CB_ELEMS 102   // 3 rows * 34 cols

__global__ __launch_bounds__(128)
void cossim_part_kernel(const float* __restrict__ xcnn) {
    const int cc   = blockIdx.x;
    const int by   = blockIdx.y;
    const int bb   = blockIdx.z;
    const int lane = threadIdx.x & 31;
    const int wrp  = threadIdx.x >> 5;
    const int y    = by * 4 + wrp;
    const int x0   = lane * 4;
    const int c0   = cc * CB_CCH;

    __shared__ float vsf[CB_CCH * CB_ELEMS];   // 25.5 KB

    int gsrc[4];
    #pragma unroll
    for (int e = 0; e < 4; e++) {
        int idx = lane + 32 * e;
        int yy = idx / 34;
        int xx = idx - yy * 34;
        int gy = min(max(by - 1 + yy, 0), 31);
        int gx = min(max(xx - 1, 0), 31);
        gsrc[e] = gy * 32 + gx;
    }
    const bool valid3 = (lane + 96) < CB_ELEMS;

    const float fy = (wrp == 0) ? 0.625f : (wrp == 1) ? 0.875f
                   : (wrp == 2) ? 0.125f : 0.375f;
    const int rb = (wrp >= 2) ? 34 : 0;

    const float* vbase = g_v + (size_t)bb * CH * VHW;
    for (int c = wrp; c < CB_CCH; c += 4) {
        const float* vc = vbase + (size_t)(c0 + c) * VHW;
        float t0 = vc[gsrc[0]];
        float t1 = vc[gsrc[1]];
        float t2 = vc[gsrc[2]];
        float* d = &vsf[c * CB_ELEMS + lane];
        d[0] = t0; d[32] = t1; d[64] = t2;
        if (valid3) d[96] = vc[gsrc[3]];
    }
    __syncthreads();

    float dot0=0.f,dot1=0.f,dot2=0.f,dot3=0.f;
    float sc0=0.f,sc1=0.f,sc2=0.f,sc3=0.f;
    float sv0=0.f,sv1=0.f,sv2=0.f,sv3=0.f;

    const float* xc = xcnn + (size_t)(bb * CH + c0) * HWOUT + (size_t)y * W_OUT + x0;

    #pragma unroll 8
    for (int c = 0; c < CB_CCH; c++) {
        float4 x4 = *(const float4*)(xc + (size_t)c * HWOUT);
        const float* v0 = &vsf[c * CB_ELEMS + rb + lane];
        float a0 = v0[0],  a1 = v0[1],  a2 = v0[2];
        float b0 = v0[34], b1 = v0[35], b2 = v0[36];
        float cv0 = fmaf(fy, b0 - a0, a0);
        float cv1 = fmaf(fy, b1 - a1, a1);
        float cv2 = fmaf(fy, b2 - a2, a2);
        float d01 = cv1 - cv0, d12 = cv2 - cv1;
        float vu0 = fmaf(0.625f, d01, cv0);
        float vu1 = fmaf(0.875f, d01, cv0);
        float vu2 = fmaf(0.125f, d12, cv1);
        float vu3 = fmaf(0.375f, d12, cv1);
        dot0 = fmaf(x4.x, vu0, dot0); sc0 = fmaf(x4.x, x4.x, sc0); sv0 = fmaf(vu0, vu0, sv0);
        dot1 = fmaf(x4.y, vu1, dot1); sc1 = fmaf(x4.y, x4.y, sc1); sv1 = fmaf(vu1, vu1, sv1);
        dot2 = fmaf(x4.z, vu2, dot2); sc2 = fmaf(x4.z, x4.z, sc2); sv2 = fmaf(vu2, vu2, sv2);
        dot3 = fmaf(x4.w, vu3, dot3); sc3 = fmaf(x4.w, x4.w, sc3); sv3 = fmaf(vu3, vu3, sv3);
    }

    const size_t pix = (size_t)y * W_OUT + x0;
    float* p = g_part + ((size_t)(cc * BATCH + bb)) * HWOUT + pix;
    const size_t sstr = (size_t)NCHUNK * BATCH * HWOUT;
    *(float4*)(p)            = make_float4(dot0, dot1, dot2, dot3);
    *(float4*)(p + sstr)     = make_float4(sc0, sc1, sc2, sc3);
    *(float4*)(p + 2 * sstr) = make_float4(sv0, sv1, sv2, sv3);
}

// ---------------------------------------------------------------------------
// Phase 2: reduce 4 chunk-partials -> cosine similarity.
// 4 px/thread, 64-thread blocks -> 512 blocks (fills 148 SMs).
// ---------------------------------------------------------------------------
__global__ __launch_bounds__(64)
void cossim_reduce_kernel(float* __restrict__ out) {
    const int gid = blockIdx.x * 64 + threadIdx.x;   // 0..32767
    const size_t pix4 = (size_t)gid * 4;
    const int bb  = (int)(pix4 >> 14);
    const size_t pix = pix4 & (HWOUT - 1);
    const size_t sstr = (size_t)NCHUNK * BATCH * HWOUT;
    const float* p = g_part + (size_t)bb * HWOUT + pix;
    const size_t cstr = (size_t)BATCH * HWOUT;

    float4 dot = make_float4(0.f, 0.f, 0.f, 0.f);
    float4 sc  = dot, sv = dot;
    #pragma unroll
    for (int cc = 0; cc < NCHUNK; cc++) {
        float4 d = *(const float4*)(p + cc * cstr);
        float4 a = *(const float4*)(p + cc * cstr + sstr);
        float4 b = *(const float4*)(p + cc * cstr + 2 * sstr);
        dot.x += d.x; dot.y += d.y; dot.z += d.z; dot.w += d.w;
        sc.x  += a.x; sc.y  += a.y; sc.z  += a.z; sc.w  += a.w;
        sv.x  += b.x; sv.y  += b.y; sv.z  += b.z; sv.w  += b.w;
    }
    float4 o;
    o.x = dot.x / (sqrtf(sc.x) * sqrtf(sv.x) + 1e-8f);
    o.y = dot.y / (sqrtf(sc.y) * sqrtf(sv.y) + 1e-8f);
    o.z = dot.z / (sqrtf(sc.z) * sqrtf(sv.z) + 1e-8f);
    o.w = dot.w / (sqrtf(sc.w) * sqrtf(sv.w) + 1e-8f);
    *(float4*)&out[pix4] = o;
}

// ---------------------------------------------------------------------------
extern "C" void kernel_launch(void* const* d_in, const int* in_sizes, int n_in,
                              void* d_out, int out_size) {
    const float* x_cnn = (const float*)d_in[0];   // [8,256,128,128]
    const float* x_vit = (const float*)d_in[1];   // [8,512,32,32]
    const float* Wmat  = (const float*)d_in[2];   // [256,512]
    const float* bias  = (const float*)d_in[3];   // [256]
    float* out = (float*)d_out;                   // [8,1,128,128]

    gemm_fused_kernel<<<dim3(VHW / 64, CH / 128, BATCH), 256>>>(x_vit, Wmat, bias);
    cossim_part_kernel<<<dim3(NCHUNK, H_OUT / 4, BATCH), 128>>>(x_cnn);
    cossim_reduce_kernel<<<dim3(BATCH * HWOUT / 4 / 64), 64>>>(out);
}

// round 10
// speedup vs baseline: 1.2884x; 1.0578x over previous
#include <cuda_runtime.h>
#include <cuda_bf16.h>
#include <cstdint>

#define BATCH 8
#define CH    256
#define KDIM  512
#define KP    256      // KDIM/2 packed bf16 pairs
#define VHW   1024     // 32*32
#define H_OUT 128
#define W_OUT 128
#define HWOUT (H_OUT * W_OUT)

// v scratch (8 MiB, L2-resident between kernels)
__device__ float g_v[BATCH * CH * VHW];
// cossim partials: [s(3)][chunk(4)][b(8)][pix] = 6.3 MB
#define NCHUNK 4
__device__ float g_part[3 * NCHUNK * BATCH * HWOUT];

// ---------------------------------------------------------------------------
// bf16 split + mma helpers
// ---------------------------------------------------------------------------
__device__ __forceinline__ void pack2(float a, float b, unsigned& hi, unsigned& lo) {
    __nv_bfloat16 ha = __float2bfloat16(a);
    __nv_bfloat16 hb = __float2bfloat16(b);
    __nv_bfloat16 la = __float2bfloat16(a - __bfloat162float(ha));
    __nv_bfloat16 lb = __float2bfloat16(b - __bfloat162float(hb));
    hi = (unsigned)__bfloat16_as_ushort(ha) | ((unsigned)__bfloat16_as_ushort(hb) << 16);
    lo = (unsigned)__bfloat16_as_ushort(la) | ((unsigned)__bfloat16_as_ushort(lb) << 16);
}

__device__ __forceinline__ void mma_bf16(float* d, const unsigned* a, unsigned b0, unsigned b1) {
    asm volatile(
        "mma.sync.aligned.m16n8k16.row.col.f32.bf16.bf16.f32 "
        "{%0,%1,%2,%3}, {%4,%5,%6,%7}, {%8,%9}, {%0,%1,%2,%3};"
        : "+f"(d[0]), "+f"(d[1]), "+f"(d[2]), "+f"(d[3])
        : "r"(a[0]), "r"(a[1]), "r"(a[2]), "r"(a[3]), "r"(b0), "r"(b1));
}

__device__ __forceinline__ void ldsm_x4(unsigned* r, unsigned saddr) {
    asm volatile(
        "ldmatrix.sync.aligned.m8n8.x4.shared.b16 {%0,%1,%2,%3}, [%4];"
        : "=r"(r[0]), "=r"(r[1]), "=r"(r[2]), "=r"(r[3]) : "r"(saddr));
}

// ---------------------------------------------------------------------------
// Fused convert + tensor-core GEMM (R8-validated, 34.4us):
// C[256,1024] = W @ X + bias per batch; bf16-split (hh + hl + lh) in one
// k-loop, fp32 reg-prefetch -> split -> STS. BM=128, BN=64, 256 thr,
// 8 warps = 4m x 2n (32x32 warp tiles), grid 256. A frags via ldmatrix.x4.
// ---------------------------------------------------------------------------
#define AS_STR 20     // ldsm rows: (m*20)%32 in {0,20,8,28,16,4,24,12} -> disjoint 16B groups
#define XS_STR 72     // X frag banks (t*72+g) -> (8t+g) distinct mod 32

__global__ __launch_bounds__(256)
void gemm_fused_kernel(const float* __restrict__ xvit,
                       const float* __restrict__ Wmat,
                       const float* __restrict__ bias) {
    const int n0 = blockIdx.x * 64;
    const int m0 = blockIdx.y * 128;
    const int bb = blockIdx.z;

    __shared__ unsigned Ash[128 * AS_STR];
    __shared__ unsigned Asl[128 * AS_STR];
    __shared__ unsigned Xsh[16 * XS_STR];
    __shared__ unsigned Xsl[16 * XS_STR];

    const int tid  = threadIdx.x;
    const int wid  = tid >> 5;
    const int lane = tid & 31;
    const int g    = lane >> 2;
    const int t4   = lane & 3;
    const int warp_m = (wid >> 1) * 32;   // 0/32/64/96
    const int warp_n = (wid & 1) * 32;    // 0/32

    const int lrow = (lane & 7) + ((lane >> 3) & 1) * 8;   // 0..15
    const int lcol = (lane >> 4) * 4;                      // 0 or 4
    const unsigned ash_u32 = (unsigned)__cvta_generic_to_shared(Ash);
    const unsigned asl_u32 = (unsigned)__cvta_generic_to_shared(Asl);

    const int arow = tid >> 1, ahalf = tid & 1;       // A: 128 rows x 2 k-halves(16)
    const int xrow = tid >> 4, xc4 = (tid & 15) * 4;  // X: 16 kp-rows x 4-n chunks

    const float* wp = Wmat + (size_t)(m0 + arow) * KDIM + ahalf * 16;
    const float* xp = xvit + ((size_t)bb * KDIM + 2 * xrow) * VHW + n0 + xc4;

    float4 wa[4];   // 16 k of W
    float4 xa[2];   // rows 2kp, 2kp+1 x 4 n

    #pragma unroll
    for (int q = 0; q < 4; q++) wa[q] = *(const float4*)(wp + 4 * q);
    xa[0] = *(const float4*)(xp);
    xa[1] = *(const float4*)(xp + VHW);

    float acc[2][4][4];
    #pragma unroll
    for (int i = 0; i < 2; i++)
        #pragma unroll
        for (int j = 0; j < 4; j++)
            #pragma unroll
            for (int q = 0; q < 4; q++) acc[i][j][q] = 0.f;

    const int NT = KP / 16;   // 16 windows of 32 k
    for (int tw = 0; tw < NT; tw++) {
        {   // A: split + STS
            uint4 h0, l0, h1, l1;
            pack2(wa[0].x, wa[0].y, h0.x, l0.x);
            pack2(wa[0].z, wa[0].w, h0.y, l0.y);
            pack2(wa[1].x, wa[1].y, h0.z, l0.z);
            pack2(wa[1].z, wa[1].w, h0.w, l0.w);
            pack2(wa[2].x, wa[2].y, h1.x, l1.x);
            pack2(wa[2].z, wa[2].w, h1.y, l1.y);
            pack2(wa[3].x, wa[3].y, h1.z, l1.z);
            pack2(wa[3].z, wa[3].w, h1.w, l1.w);
            unsigned* dh = &Ash[arow * AS_STR + ahalf * 8];
            unsigned* dl = &Asl[arow * AS_STR + ahalf * 8];
            *(uint4*)dh = h0; *(uint4*)(dh + 4) = h1;
            *(uint4*)dl = l0; *(uint4*)(dl + 4) = l1;
        }
        {   // X: split + STS (k-pair rows packed)
            uint4 h, l;
            pack2(xa[0].x, xa[1].x, h.x, l.x);
            pack2(xa[0].y, xa[1].y, h.y, l.y);
            pack2(xa[0].z, xa[1].z, h.z, l.z);
            pack2(xa[0].w, xa[1].w, h.w, l.w);
            *(uint4*)&Xsh[xrow * XS_STR + xc4] = h;
            *(uint4*)&Xsl[xrow * XS_STR + xc4] = l;
        }
        __syncthreads();

        if (tw < NT - 1) {   // prefetch next window (overlaps MMA)
            const float* wpn = wp + (tw + 1) * 32;
            const float* xpn = xp + (size_t)(tw + 1) * 32 * VHW;
            #pragma unroll
            for (int q = 0; q < 4; q++) wa[q] = *(const float4*)(wpn + 4 * q);
            xa[0] = *(const float4*)(xpn);
            xa[1] = *(const float4*)(xpn + VHW);
        }

        #pragma unroll
        for (int kb = 0; kb < 2; kb++) {
            unsigned ah[2][4], al[2][4];
            #pragma unroll
            for (int mt = 0; mt < 2; mt++) {
                const unsigned off =
                    (unsigned)(((warp_m + mt * 16 + lrow) * AS_STR + kb * 8 + lcol) * 4);
                ldsm_x4(ah[mt], ash_u32 + off);
                ldsm_x4(al[mt], asl_u32 + off);
            }
            #pragma unroll
            for (int nt = 0; nt < 4; nt++) {
                const int xb = (kb * 8 + t4) * XS_STR + warp_n + nt * 8 + g;
                unsigned bh0 = Xsh[xb];
                unsigned bh1 = Xsh[xb + 4 * XS_STR];
                unsigned bl0 = Xsl[xb];
                unsigned bl1 = Xsl[xb + 4 * XS_STR];
                #pragma unroll
                for (int mt = 0; mt < 2; mt++) {
                    mma_bf16(acc[mt][nt], ah[mt], bh0, bh1);  // hh
                    mma_bf16(acc[mt][nt], ah[mt], bl0, bl1);  // hl
                    mma_bf16(acc[mt][nt], al[mt], bh0, bh1);  // lh
                }
            }
        }
        __syncthreads();
    }

    // epilogue
    float* Cg = g_v + (size_t)bb * CH * VHW;
    #pragma unroll
    for (int mt = 0; mt < 2; mt++) {
        const int r0 = m0 + warp_m + mt * 16 + g;
        const float bv0 = bias[r0];
        const float bv1 = bias[r0 + 8];
        #pragma unroll
        for (int nt = 0; nt < 4; nt++) {
            const int c = n0 + warp_n + nt * 8 + 2 * t4;
            *(float2*)&Cg[(size_t)r0 * VHW + c] =
                make_float2(acc[mt][nt][0] + bv0, acc[mt][nt][1] + bv0);
            *(float2*)&Cg[(size_t)(r0 + 8) * VHW + c] =
                make_float2(acc[mt][nt][2] + bv1, acc[mt][nt][3] + bv1);
        }
    }
}

// ---------------------------------------------------------------------------
// Phase 1: fused bilinear + partial cossim over a 64-channel chunk.
// grid (4, 32, 8) = 1024 blocks, 128 thr; 128(w)x4(h) tile, 4 px/thread.
// NEW: explicit 8-deep register prefetch FIFO on the x_cnn stream (forces
// MLP>=8 per thread) + __ldcs streaming loads (zero-reuse data, evict-first).
// ---------------------------------------------------------------------------
#define CB_CCH   64
#define CB_ELEMS 102   // 3 rows * 34 cols
#define PF       8

__global__ __launch_bounds__(128)
void cossim_part_kernel(const float* __restrict__ xcnn) {
    const int cc   = blockIdx.x;
    const int by   = blockIdx.y;
    const int bb   = blockIdx.z;
    const int lane = threadIdx.x & 31;
    const int wrp  = threadIdx.x >> 5;
    const int y    = by * 4 + wrp;
    const int x0   = lane * 4;
    const int c0   = cc * CB_CCH;

    __shared__ float vsf[CB_CCH * CB_ELEMS];   // 25.5 KB

    int gsrc[4];
    #pragma unroll
    for (int e = 0; e < 4; e++) {
        int idx = lane + 32 * e;
        int yy = idx / 34;
        int xx = idx - yy * 34;
        int gy = min(max(by - 1 + yy, 0), 31);
        int gx = min(max(xx - 1, 0), 31);
        gsrc[e] = gy * 32 + gx;
    }
    const bool valid3 = (lane + 96) < CB_ELEMS;

    const float fy = (wrp == 0) ? 0.625f : (wrp == 1) ? 0.875f
                   : (wrp == 2) ? 0.125f : 0.375f;
    const int rb = (wrp >= 2) ? 34 : 0;

    const float* xc = xcnn + (size_t)(bb * CH + c0) * HWOUT + (size_t)y * W_OUT + x0;

    // start the x_cnn prefetch FIFO BEFORE staging (overlaps v gather)
    float4 xq[PF];
    #pragma unroll
    for (int i = 0; i < PF; i++)
        xq[i] = __ldcs((const float4*)(xc + (size_t)i * HWOUT));

    const float* vbase = g_v + (size_t)bb * CH * VHW;
    for (int c = wrp; c < CB_CCH; c += 4) {
        const float* vc = vbase + (size_t)(c0 + c) * VHW;
        float t0 = vc[gsrc[0]];
        float t1 = vc[gsrc[1]];
        float t2 = vc[gsrc[2]];
        float* d = &vsf[c * CB_ELEMS + lane];
        d[0] = t0; d[32] = t1; d[64] = t2;
        if (valid3) d[96] = vc[gsrc[3]];
    }
    __syncthreads();

    float dot0=0.f,dot1=0.f,dot2=0.f,dot3=0.f;
    float sc0=0.f,sc1=0.f,sc2=0.f,sc3=0.f;
    float sv0=0.f,sv1=0.f,sv2=0.f,sv3=0.f;

    #pragma unroll 8
    for (int c = 0; c < CB_CCH; c++) {
        float4 x4 = xq[c & (PF - 1)];
        if (c + PF < CB_CCH)
            xq[c & (PF - 1)] = __ldcs((const float4*)(xc + (size_t)(c + PF) * HWOUT));
        const float* v0 = &vsf[c * CB_ELEMS + rb + lane];
        float a0 = v0[0],  a1 = v0[1],  a2 = v0[2];
        float b0 = v0[34], b1 = v0[35], b2 = v0[36];
        float cv0 = fmaf(fy, b0 - a0, a0);
        float cv1 = fmaf(fy, b1 - a1, a1);
        float cv2 = fmaf(fy, b2 - a2, a2);
        float d01 = cv1 - cv0, d12 = cv2 - cv1;
        float vu0 = fmaf(0.625f, d01, cv0);
        float vu1 = fmaf(0.875f, d01, cv0);
        float vu2 = fmaf(0.125f, d12, cv1);
        float vu3 = fmaf(0.375f, d12, cv1);
        dot0 = fmaf(x4.x, vu0, dot0); sc0 = fmaf(x4.x, x4.x, sc0); sv0 = fmaf(vu0, vu0, sv0);
        dot1 = fmaf(x4.y, vu1, dot1); sc1 = fmaf(x4.y, x4.y, sc1); sv1 = fmaf(vu1, vu1, sv1);
        dot2 = fmaf(x4.z, vu2, dot2); sc2 = fmaf(x4.z, x4.z, sc2); sv2 = fmaf(vu2, vu2, sv2);
        dot3 = fmaf(x4.w, vu3, dot3); sc3 = fmaf(x4.w, x4.w, sc3); sv3 = fmaf(vu3, vu3, sv3);
    }

    const size_t pix = (size_t)y * W_OUT + x0;
    float* p = g_part + ((size_t)(cc * BATCH + bb)) * HWOUT + pix;
    const size_t sstr = (size_t)NCHUNK * BATCH * HWOUT;
    *(float4*)(p)            = make_float4(dot0, dot1, dot2, dot3);
    *(float4*)(p + sstr)     = make_float4(sc0, sc1, sc2, sc3);
    *(float4*)(p + 2 * sstr) = make_float4(sv0, sv1, sv2, sv3);
}

// ---------------------------------------------------------------------------
// Phase 2: reduce 4 chunk-partials -> cosine similarity.
// 4 px/thread, 64-thread blocks -> 512 blocks.
// ---------------------------------------------------------------------------
__global__ __launch_bounds__(64)
void cossim_reduce_kernel(float* __restrict__ out) {
    const int gid = blockIdx.x * 64 + threadIdx.x;
    const size_t pix4 = (size_t)gid * 4;
    const int bb  = (int)(pix4 >> 14);
    const size_t pix = pix4 & (HWOUT - 1);
    const size_t sstr = (size_t)NCHUNK * BATCH * HWOUT;
    const float* p = g_part + (size_t)bb * HWOUT + pix;
    const size_t cstr = (size_t)BATCH * HWOUT;

    float4 dot = make_float4(0.f, 0.f, 0.f, 0.f);
    float4 sc  = dot, sv = dot;
    #pragma unroll
    for (int cc = 0; cc < NCHUNK; cc++) {
        float4 d = *(const float4*)(p + cc * cstr);
        float4 a = *(const float4*)(p + cc * cstr + sstr);
        float4 b = *(const float4*)(p + cc * cstr + 2 * sstr);
        dot.x += d.x; dot.y += d.y; dot.z += d.z; dot.w += d.w;
        sc.x  += a.x; sc.y  += a.y; sc.z  += a.z; sc.w  += a.w;
        sv.x  += b.x; sv.y  += b.y; sv.z  += b.z; sv.w  += b.w;
    }
    float4 o;
    o.x = dot.x / (sqrtf(sc.x) * sqrtf(sv.x) + 1e-8f);
    o.y = dot.y / (sqrtf(sc.y) * sqrtf(sv.y) + 1e-8f);
    o.z = dot.z / (sqrtf(sc.z) * sqrtf(sv.z) + 1e-8f);
    o.w = dot.w / (sqrtf(sc.w) * sqrtf(sv.w) + 1e-8f);
    *(float4*)&out[pix4] = o;
}

// ---------------------------------------------------------------------------
extern "C" void kernel_launch(void* const* d_in, const int* in_sizes, int n_in,
                              void* d_out, int out_size) {
    const float* x_cnn = (const float*)d_in[0];   // [8,256,128,128]
    const float* x_vit = (const float*)d_in[1];   // [8,512,32,32]
    const float* Wmat  = (const float*)d_in[2];   // [256,512]
    const float* bias  = (const float*)d_in[3];   // [256]
    float* out = (float*)d_out;                   // [8,1,128,128]

    gemm_fused_kernel<<<dim3(VHW / 64, CH / 128, BATCH), 256>>>(x_vit, Wmat, bias);
    cossim_part_kernel<<<dim3(NCHUNK, H_OUT / 4, BATCH), 128>>>(x_cnn);
    cossim_reduce_kernel<<<dim3(BATCH * HWOUT / 4 / 64), 64>>>(out);
}

// round 14
// speedup vs baseline: 1.3614x; 1.0567x over previous
#include <cuda_runtime.h>
#include <cuda_bf16.h>
#include <cstdint>

#define BATCH 8
#define CH    256
#define KDIM  512
#define KP    256      // KDIM/2 packed bf16 pairs
#define VHW   1024     // 32*32
#define H_OUT 128
#define W_OUT 128
#define HWOUT (H_OUT * W_OUT)

// v scratch (8 MiB, L2-resident between kernels)
__device__ float g_v[BATCH * CH * VHW];
// cossim partials: [s(3)][chunk(4)][b(8)][pix] = 6.3 MB
#define NCHUNK 4
__device__ float g_part[3 * NCHUNK * BATCH * HWOUT];

// ---------------------------------------------------------------------------
// bf16 split + mma helpers
// ---------------------------------------------------------------------------
__device__ __forceinline__ void pack2(float a, float b, unsigned& hi, unsigned& lo) {
    __nv_bfloat16 ha = __float2bfloat16(a);
    __nv_bfloat16 hb = __float2bfloat16(b);
    __nv_bfloat16 la = __float2bfloat16(a - __bfloat162float(ha));
    __nv_bfloat16 lb = __float2bfloat16(b - __bfloat162float(hb));
    hi = (unsigned)__bfloat16_as_ushort(ha) | ((unsigned)__bfloat16_as_ushort(hb) << 16);
    lo = (unsigned)__bfloat16_as_ushort(la) | ((unsigned)__bfloat16_as_ushort(lb) << 16);
}

__device__ __forceinline__ void mma_bf16(float* d, const unsigned* a, unsigned b0, unsigned b1) {
    asm volatile(
        "mma.sync.aligned.m16n8k16.row.col.f32.bf16.bf16.f32 "
        "{%0,%1,%2,%3}, {%4,%5,%6,%7}, {%8,%9}, {%0,%1,%2,%3};"
        : "+f"(d[0]), "+f"(d[1]), "+f"(d[2]), "+f"(d[3])
        : "r"(a[0]), "r"(a[1]), "r"(a[2]), "r"(a[3]), "r"(b0), "r"(b1));
}

__device__ __forceinline__ void ldsm_x4(unsigned* r, unsigned saddr) {
    asm volatile(
        "ldmatrix.sync.aligned.m8n8.x4.shared.b16 {%0,%1,%2,%3}, [%4];"
        : "=r"(r[0]), "=r"(r[1]), "=r"(r[2]), "=r"(r[3]) : "r"(saddr));
}

// ---------------------------------------------------------------------------
// Fused convert + tensor-core GEMM: C[256,1024] = W @ X + bias per batch.
// bf16-split (hh + hl + lh), fp32 reg-prefetch -> split -> STS.
// BM=128, BN=64, 256 thr, 8 warps = 4m x 2n (32x32 warp tiles), grid 256.
// NEW: X stored transposed [n][kp] so BOTH operands' fragments load via
// ldmatrix.x4 (B path: 32 scalar LDS -> 8 LDSM per warp/window).
// ---------------------------------------------------------------------------
#define AS_STR 20     // ldsm rows: (m*20)%32 in {0,20,8,28,16,4,24,12} -> disjoint 16B groups
#define XT_STR 20     // same conflict-free pattern for X rows (n-major)

__global__ __launch_bounds__(256)
void gemm_fused_kernel(const float* __restrict__ xvit,
                       const float* __restrict__ Wmat,
                       const float* __restrict__ bias) {
    const int n0 = blockIdx.x * 64;
    const int m0 = blockIdx.y * 128;
    const int bb = blockIdx.z;

    __shared__ unsigned Ash[128 * AS_STR];
    __shared__ unsigned Asl[128 * AS_STR];
    __shared__ unsigned Xth[64 * XT_STR];   // [n][kp window 16]
    __shared__ unsigned Xtl[64 * XT_STR];

    const int tid  = threadIdx.x;
    const int wid  = tid >> 5;
    const int lane = tid & 31;
    const int g    = lane >> 2;
    const int t4   = lane & 3;
    const int warp_m = (wid >> 1) * 32;   // 0/32/64/96
    const int warp_n = (wid & 1) * 32;    // 0/32

    // ldmatrix lane-address components (A)
    const int lrow = (lane & 7) + ((lane >> 3) & 1) * 8;   // 0..15
    const int lcol = (lane >> 4) * 4;                      // 0 or 4
    const unsigned ash_u32 = (unsigned)__cvta_generic_to_shared(Ash);
    const unsigned asl_u32 = (unsigned)__cvta_generic_to_shared(Asl);
    // ldmatrix lane-address components (B): matrix j=(lane>>3) = (nt-half, b0/b1)
    const int bj = lane >> 3;
    const int br = lane & 7;
    const unsigned xth_u32 = (unsigned)__cvta_generic_to_shared(Xth);
    const unsigned xtl_u32 = (unsigned)__cvta_generic_to_shared(Xtl);
    const unsigned xbase =
        (unsigned)(((warp_n + (bj >> 1) * 8 + br) * XT_STR + (bj & 1) * 4) * 4);
    // addr(q, kb) = x??_u32 + xbase + q*16*XT_STR*4 + kb*32

    // staging indices
    const int arow = tid >> 1, ahalf = tid & 1;   // A: 128 rows x 2 k-halves(16)
    const int xn   = tid & 63;                    // X: n column 0..63
    const int kpb  = tid >> 6;                    // X: kp block 0..3 (4 kp = 8 k)

    const float* wp = Wmat + (size_t)(m0 + arow) * KDIM + ahalf * 16;
    const float* xp = xvit + ((size_t)bb * KDIM + kpb * 8) * VHW + n0 + xn;

    float4 wa[4];   // 16 k of W
    float  xv[8];   // 8 k rows of one n column

    #pragma unroll
    for (int q = 0; q < 4; q++) wa[q] = *(const float4*)(wp + 4 * q);
    #pragma unroll
    for (int j = 0; j < 8; j++) xv[j] = xp[(size_t)j * VHW];

    float acc[2][4][4];
    #pragma unroll
    for (int i = 0; i < 2; i++)
        #pragma unroll
        for (int j = 0; j < 4; j++)
            #pragma unroll
            for (int q = 0; q < 4; q++) acc[i][j][q] = 0.f;

    const int NT = KP / 16;   // 16 windows of 32 k
    for (int tw = 0; tw < NT; tw++) {
        {   // A: split + STS
            uint4 h0, l0, h1, l1;
            pack2(wa[0].x, wa[0].y, h0.x, l0.x);
            pack2(wa[0].z, wa[0].w, h0.y, l0.y);
            pack2(wa[1].x, wa[1].y, h0.z, l0.z);
            pack2(wa[1].z, wa[1].w, h0.w, l0.w);
            pack2(wa[2].x, wa[2].y, h1.x, l1.x);
            pack2(wa[2].z, wa[2].w, h1.y, l1.y);
            pack2(wa[3].x, wa[3].y, h1.z, l1.z);
            pack2(wa[3].z, wa[3].w, h1.w, l1.w);
            unsigned* dh = &Ash[arow * AS_STR + ahalf * 8];
            unsigned* dl = &Asl[arow * AS_STR + ahalf * 8];
            *(uint4*)dh = h0; *(uint4*)(dh + 4) = h1;
            *(uint4*)dl = l0; *(uint4*)(dl + 4) = l1;
        }
        {   // X: split + STS transposed (one n, 4 kp words)
            uint4 h, l;
            pack2(xv[0], xv[1], h.x, l.x);
            pack2(xv[2], xv[3], h.y, l.y);
            pack2(xv[4], xv[5], h.z, l.z);
            pack2(xv[6], xv[7], h.w, l.w);
            *(uint4*)&Xth[xn * XT_STR + kpb * 4] = h;
            *(uint4*)&Xtl[xn * XT_STR + kpb * 4] = l;
        }
        __syncthreads();

        if (tw < NT - 1) {   // prefetch next window (overlaps MMA)
            const float* wpn = wp + (tw + 1) * 32;
            const float* xpn = xp + (size_t)((tw + 1) * 32) * VHW;
            #pragma unroll
            for (int q = 0; q < 4; q++) wa[q] = *(const float4*)(wpn + 4 * q);
            #pragma unroll
            for (int j = 0; j < 8; j++) xv[j] = xpn[(size_t)j * VHW];
        }

        #pragma unroll
        for (int kb = 0; kb < 2; kb++) {
            unsigned ah[2][4], al[2][4];
            #pragma unroll
            for (int mt = 0; mt < 2; mt++) {
                const unsigned off =
                    (unsigned)(((warp_m + mt * 16 + lrow) * AS_STR + kb * 8 + lcol) * 4);
                ldsm_x4(ah[mt], ash_u32 + off);
                ldsm_x4(al[mt], asl_u32 + off);
            }
            unsigned bh[8], bl[8];
            ldsm_x4(bh,     xth_u32 + xbase + kb * 32);
            ldsm_x4(bh + 4, xth_u32 + xbase + 16 * XT_STR * 4 + kb * 32);
            ldsm_x4(bl,     xtl_u32 + xbase + kb * 32);
            ldsm_x4(bl + 4, xtl_u32 + xbase + 16 * XT_STR * 4 + kb * 32);
            #pragma unroll
            for (int nt = 0; nt < 4; nt++) {
                unsigned bh0 = bh[2 * nt], bh1 = bh[2 * nt + 1];
                unsigned bl0 = bl[2 * nt], bl1 = bl[2 * nt + 1];
                #pragma unroll
                for (int mt = 0; mt < 2; mt++) {
                    mma_bf16(acc[mt][nt], ah[mt], bh0, bh1);  // hh
                    mma_bf16(acc[mt][nt], ah[mt], bl0, bl1);  // hl
                    mma_bf16(acc[mt][nt], al[mt], bh0, bh1);  // lh
                }
            }
        }
        __syncthreads();
    }

    // epilogue
    float* Cg = g_v + (size_t)bb * CH * VHW;
    #pragma unroll
    for (int mt = 0; mt < 2; mt++) {
        const int r0 = m0 + warp_m + mt * 16 + g;
        const float bv0 = bias[r0];
        const float bv1 = bias[r0 + 8];
        #pragma unroll
        for (int nt = 0; nt < 4; nt++) {
            const int c = n0 + warp_n + nt * 8 + 2 * t4;
            *(float2*)&Cg[(size_t)r0 * VHW + c] =
                make_float2(acc[mt][nt][0] + bv0, acc[mt][nt][1] + bv0);
            *(float2*)&Cg[(size_t)(r0 + 8) * VHW + c] =
                make_float2(acc[mt][nt][2] + bv1, acc[mt][nt][3] + bv1);
        }
    }
}

// ---------------------------------------------------------------------------
// Phase 1: fused bilinear + partial cossim over a 64-channel chunk.
// grid (4, 32, 8) = 1024 blocks, 128 thr; 128(w)x4(h) tile, 4 px/thread.
// 8-deep register prefetch FIFO on x_cnn + __ldcs streaming. (R10-validated.)
// ---------------------------------------------------------------------------
#define CB_CCH   64
#define CB_ELEMS 102   // 3 rows * 34 cols
#define PF       8

__global__ __launch_bounds__(128)
void cossim_part_kernel(const float* __restrict__ xcnn) {
    const int cc   = blockIdx.x;
    const int by   = blockIdx.y;
    const int bb   = blockIdx.z;
    const int lane = threadIdx.x & 31;
    const int wrp  = threadIdx.x >> 5;
    const int y    = by * 4 + wrp;
    const int x0   = lane * 4;
    const int c0   = cc * CB_CCH;

    __shared__ float vsf[CB_CCH * CB_ELEMS];   // 25.5 KB

    int gsrc[4];
    #pragma unroll
    for (int e = 0; e < 4; e++) {
        int idx = lane + 32 * e;
        int yy = idx / 34;
        int xx = idx - yy * 34;
        int gy = min(max(by - 1 + yy, 0), 31);
        int gx = min(max(xx - 1, 0), 31);
        gsrc[e] = gy * 32 + gx;
    }
    const bool valid3 = (lane + 96) < CB_ELEMS;

    const float fy = (wrp == 0) ? 0.625f : (wrp == 1) ? 0.875f
                   : (wrp == 2) ? 0.125f : 0.375f;
    const int rb = (wrp >= 2) ? 34 : 0;

    const float* xc = xcnn + (size_t)(bb * CH + c0) * HWOUT + (size_t)y * W_OUT + x0;

    // start the x_cnn prefetch FIFO BEFORE staging (overlaps v gather)
    float4 xq[PF];
    #pragma unroll
    for (int i = 0; i < PF; i++)
        xq[i] = __ldcs((const float4*)(xc + (size_t)i * HWOUT));

    const float* vbase = g_v + (size_t)bb * CH * VHW;
    for (int c = wrp; c < CB_CCH; c += 4) {
        const float* vc = vbase + (size_t)(c0 + c) * VHW;
        float t0 = vc[gsrc[0]];
        float t1 = vc[gsrc[1]];
        float t2 = vc[gsrc[2]];
        float* d = &vsf[c * CB_ELEMS + lane];
        d[0] = t0; d[32] = t1; d[64] = t2;
        if (valid3) d[96] = vc[gsrc[3]];
    }
    __syncthreads();

    float dot0=0.f,dot1=0.f,dot2=0.f,dot3=0.f;
    float sc0=0.f,sc1=0.f,sc2=0.f,sc3=0.f;
    float sv0=0.f,sv1=0.f,sv2=0.f,sv3=0.f;

    #pragma unroll 8
    for (int c = 0; c < CB_CCH; c++) {
        float4 x4 = xq[c & (PF - 1)];
        if (c + PF < CB_CCH)
            xq[c & (PF - 1)] = __ldcs((const float4*)(xc + (size_t)(c + PF) * HWOUT));
        const float* v0 = &vsf[c * CB_ELEMS + rb + lane];
        float a0 = v0[0],  a1 = v0[1],  a2 = v0[2];
        float b0 = v0[34], b1 = v0[35], b2 = v0[36];
        float cv0 = fmaf(fy, b0 - a0, a0);
        float cv1 = fmaf(fy, b1 - a1, a1);
        float cv2 = fmaf(fy, b2 - a2, a2);
        float d01 = cv1 - cv0, d12 = cv2 - cv1;
        float vu0 = fmaf(0.625f, d01, cv0);
        float vu1 = fmaf(0.875f, d01, cv0);
        float vu2 = fmaf(0.125f, d12, cv1);
        float vu3 = fmaf(0.375f, d12, cv1);
        dot0 = fmaf(x4.x, vu0, dot0); sc0 = fmaf(x4.x, x4.x, sc0); sv0 = fmaf(vu0, vu0, sv0);
        dot1 = fmaf(x4.y, vu1, dot1); sc1 = fmaf(x4.y, x4.y, sc1); sv1 = fmaf(vu1, vu1, sv1);
        dot2 = fmaf(x4.z, vu2, dot2); sc2 = fmaf(x4.z, x4.z, sc2); sv2 = fmaf(vu2, vu2, sv2);
        dot3 = fmaf(x4.w, vu3, dot3); sc3 = fmaf(x4.w, x4.w, sc3); sv3 = fmaf(vu3, vu3, sv3);
    }

    const size_t pix = (size_t)y * W_OUT + x0;
    float* p = g_part + ((size_t)(cc * BATCH + bb)) * HWOUT + pix;
    const size_t sstr = (size_t)NCHUNK * BATCH * HWOUT;
    *(float4*)(p)            = make_float4(dot0, dot1, dot2, dot3);
    *(float4*)(p + sstr)     = make_float4(sc0, sc1, sc2, sc3);
    *(float4*)(p + 2 * sstr) = make_float4(sv0, sv1, sv2, sv3);
}

// ---------------------------------------------------------------------------
// Phase 2: reduce 4 chunk-partials -> cosine similarity.
// 4 px/thread, 64-thread blocks -> 512 blocks.
// ---------------------------------------------------------------------------
__global__ __launch_bounds__(64)
void cossim_reduce_kernel(float* __restrict__ out) {
    const int gid = blockIdx.x * 64 + threadIdx.x;
    const size_t pix4 = (size_t)gid * 4;
    const int bb  = (int)(pix4 >> 14);
    const size_t pix = pix4 & (HWOUT - 1);
    const size_t sstr = (size_t)NCHUNK * BATCH * HWOUT;
    const float* p = g_part + (size_t)bb * HWOUT + pix;
    const size_t cstr = (size_t)BATCH * HWOUT;

    float4 dot = make_float4(0.f, 0.f, 0.f, 0.f);
    float4 sc  = dot, sv = dot;
    #pragma unroll
    for (int cc = 0; cc < NCHUNK; cc++) {
        float4 d = *(const float4*)(p + cc * cstr);
        float4 a = *(const float4*)(p + cc * cstr + sstr);
        float4 b = *(const float4*)(p + cc * cstr + 2 * sstr);
        dot.x += d.x; dot.y += d.y; dot.z += d.z; dot.w += d.w;
        sc.x  += a.x; sc.y  += a.y; sc.z  += a.z; sc.w  += a.w;
        sv.x  += b.x; sv.y  += b.y; sv.z  += b.z; sv.w  += b.w;
    }
    float4 o;
    o.x = dot.x / (sqrtf(sc.x) * sqrtf(sv.x) + 1e-8f);
    o.y = dot.y / (sqrtf(sc.y) * sqrtf(sv.y) + 1e-8f);
    o.z = dot.z / (sqrtf(sc.z) * sqrtf(sv.z) + 1e-8f);
    o.w = dot.w / (sqrtf(sc.w) * sqrtf(sv.w) + 1e-8f);
    *(float4*)&out[pix4] = o;
}

// ---------------------------------------------------------------------------
extern "C" void kernel_launch(void* const* d_in, const int* in_sizes, int n_in,
                              void* d_out, int out_size) {
    const float* x_cnn = (const float*)d_in[0];   // [8,256,128,128]
    const float* x_vit = (const float*)d_in[1];   // [8,512,32,32]
    const float* Wmat  = (const float*)d_in[2];   // [256,512]
    const float* bias  = (const float*)d_in[3];   // [256]
    float* out = (float*)d_out;                   // [8,1,128,128]

    gemm_fused_kernel<<<dim3(VHW / 64, CH / 128, BATCH), 256>>>(x_vit, Wmat, bias);
    cossim_part_kernel<<<dim3(NCHUNK, H_OUT / 4, BATCH), 128>>>(x_cnn);
    cossim_reduce_kernel<<<dim3(BATCH * HWOUT / 4 / 64), 64>>>(out);
}

// round 15
// speedup vs baseline: 1.4050x; 1.0320x over previous
#include <cuda_runtime.h>
#include <cuda_bf16.h>
#include <cstdint>

#define BATCH 8
#define CH    256
#define KDIM  512
#define KP    256      // KDIM/2 packed bf16 pairs
#define VHW   1024     // 32*32
#define H_OUT 128
#define W_OUT 128
#define HWOUT (H_OUT * W_OUT)

// v scratch (8 MiB, L2-resident between kernels)
__device__ float g_v[BATCH * CH * VHW];
// cossim partials: [s(3)][chunk(8)][b(8)][pix] = 12.6 MB
#define NCHUNK 8
__device__ float g_part[3 * NCHUNK * BATCH * HWOUT];

// ---------------------------------------------------------------------------
// bf16 split + mma helpers
// ---------------------------------------------------------------------------
__device__ __forceinline__ void pack2(float a, float b, unsigned& hi, unsigned& lo) {
    __nv_bfloat16 ha = __float2bfloat16(a);
    __nv_bfloat16 hb = __float2bfloat16(b);
    __nv_bfloat16 la = __float2bfloat16(a - __bfloat162float(ha));
    __nv_bfloat16 lb = __float2bfloat16(b - __bfloat162float(hb));
    hi = (unsigned)__bfloat16_as_ushort(ha) | ((unsigned)__bfloat16_as_ushort(hb) << 16);
    lo = (unsigned)__bfloat16_as_ushort(la) | ((unsigned)__bfloat16_as_ushort(lb) << 16);
}

__device__ __forceinline__ void mma_bf16(float* d, const unsigned* a, unsigned b0, unsigned b1) {
    asm volatile(
        "mma.sync.aligned.m16n8k16.row.col.f32.bf16.bf16.f32 "
        "{%0,%1,%2,%3}, {%4,%5,%6,%7}, {%8,%9}, {%0,%1,%2,%3};"
        : "+f"(d[0]), "+f"(d[1]), "+f"(d[2]), "+f"(d[3])
        : "r"(a[0]), "r"(a[1]), "r"(a[2]), "r"(a[3]), "r"(b0), "r"(b1));
}

__device__ __forceinline__ void ldsm_x4(unsigned* r, unsigned saddr) {
    asm volatile(
        "ldmatrix.sync.aligned.m8n8.x4.shared.b16 {%0,%1,%2,%3}, [%4];"
        : "=r"(r[0]), "=r"(r[1]), "=r"(r[2]), "=r"(r[3]) : "r"(saddr));
}

// ---------------------------------------------------------------------------
// Fused convert + tensor-core GEMM: C[256,1024] = W @ X + bias per batch.
// bf16-split (hh + hl + lh), fp32 reg-prefetch -> split -> STS.
// BM=128, BN=64, 256 thr, 8 warps = 4m x 2n (32x32 warp tiles), grid 256.
// Both operands' fragments via ldmatrix.x4 (R14-validated layouts).
// NEW: double-buffered smem -> ONE sync per 32-k window; STS overlaps MMA.
// ---------------------------------------------------------------------------
#define AS_STR 20     // ldsm rows: (m*20)%32 in {0,20,8,28,16,4,24,12} -> disjoint 16B groups
#define XT_STR 20     // same conflict-free pattern for X rows (n-major)

__global__ __launch_bounds__(256)
void gemm_fused_kernel(const float* __restrict__ xvit,
                       const float* __restrict__ Wmat,
                       const float* __restrict__ bias) {
    const int n0 = blockIdx.x * 64;
    const int m0 = blockIdx.y * 128;
    const int bb = blockIdx.z;

    __shared__ unsigned Ash[2][128 * AS_STR];
    __shared__ unsigned Asl[2][128 * AS_STR];
    __shared__ unsigned Xth[2][64 * XT_STR];   // [n][kp window 16]
    __shared__ unsigned Xtl[2][64 * XT_STR];

    const int tid  = threadIdx.x;
    const int wid  = tid >> 5;
    const int lane = tid & 31;
    const int g    = lane >> 2;
    const int t4   = lane & 3;
    const int warp_m = (wid >> 1) * 32;   // 0/32/64/96
    const int warp_n = (wid & 1) * 32;    // 0/32

    // ldmatrix lane-address components (A)
    const int lrow = (lane & 7) + ((lane >> 3) & 1) * 8;   // 0..15
    const int lcol = (lane >> 4) * 4;                      // 0 or 4
    const unsigned aoff =
        (unsigned)(((warp_m + lrow) * AS_STR + lcol) * 4);
    const unsigned ash_u32 = (unsigned)__cvta_generic_to_shared(&Ash[0][0]);
    const unsigned asl_u32 = (unsigned)__cvta_generic_to_shared(&Asl[0][0]);
    // ldmatrix lane-address components (B)
    const int bj = lane >> 3;
    const int br = lane & 7;
    const unsigned xth_u32 = (unsigned)__cvta_generic_to_shared(&Xth[0][0]);
    const unsigned xtl_u32 = (unsigned)__cvta_generic_to_shared(&Xtl[0][0]);
    const unsigned xbase =
        (unsigned)(((warp_n + (bj >> 1) * 8 + br) * XT_STR + (bj & 1) * 4) * 4);

    // staging indices
    const int arow = tid >> 1, ahalf = tid & 1;   // A: 128 rows x 2 k-halves(16)
    const int xn   = tid & 63;                    // X: n column 0..63
    const int kpb  = tid >> 6;                    // X: kp block 0..3 (4 kp = 8 k)

    const float* wp = Wmat + (size_t)(m0 + arow) * KDIM + ahalf * 16;
    const float* xp = xvit + ((size_t)bb * KDIM + kpb * 8) * VHW + n0 + xn;

    float4 wa[4];   // 16 k of W
    float  xv[8];   // 8 k rows of one n column

    #define LOADW(tw) do { \
        const float* wpn_ = wp + (tw) * 32; \
        const float* xpn_ = xp + (size_t)((tw) * 32) * VHW; \
        _Pragma("unroll") \
        for (int q = 0; q < 4; q++) wa[q] = *(const float4*)(wpn_ + 4 * q); \
        _Pragma("unroll") \
        for (int j = 0; j < 8; j++) xv[j] = xpn_[(size_t)j * VHW]; \
    } while (0)

    #define STSW(bf) do { \
        uint4 h0, l0, h1, l1; \
        pack2(wa[0].x, wa[0].y, h0.x, l0.x); \
        pack2(wa[0].z, wa[0].w, h0.y, l0.y); \
        pack2(wa[1].x, wa[1].y, h0.z, l0.z); \
        pack2(wa[1].z, wa[1].w, h0.w, l0.w); \
        pack2(wa[2].x, wa[2].y, h1.x, l1.x); \
        pack2(wa[2].z, wa[2].w, h1.y, l1.y); \
        pack2(wa[3].x, wa[3].y, h1.z, l1.z); \
        pack2(wa[3].z, wa[3].w, h1.w, l1.w); \
        unsigned* dh = &Ash[bf][arow * AS_STR + ahalf * 8]; \
        unsigned* dl = &Asl[bf][arow * AS_STR + ahalf * 8]; \
        *(uint4*)dh = h0; *(uint4*)(dh + 4) = h1; \
        *(uint4*)dl = l0; *(uint4*)(dl + 4) = l1; \
        uint4 xh, xl; \
        pack2(xv[0], xv[1], xh.x, xl.x); \
        pack2(xv[2], xv[3], xh.y, xl.y); \
        pack2(xv[4], xv[5], xh.z, xl.z); \
        pack2(xv[6], xv[7], xh.w, xl.w); \
        *(uint4*)&Xth[bf][xn * XT_STR + kpb * 4] = xh; \
        *(uint4*)&Xtl[bf][xn * XT_STR + kpb * 4] = xl; \
    } while (0)

    float acc[2][4][4];
    #pragma unroll
    for (int i = 0; i < 2; i++)
        #pragma unroll
        for (int j = 0; j < 4; j++)
            #pragma unroll
            for (int q = 0; q < 4; q++) acc[i][j][q] = 0.f;

    const int NT = KP / 16;   // 16 windows of 32 k
    const unsigned ABUF = 128 * AS_STR * 4;   // byte stride between A buffers
    const unsigned XBUF = 64 * XT_STR * 4;

    LOADW(0);
    STSW(0);
    LOADW(1);
    __syncthreads();

    for (int tw = 0; tw < NT; tw++) {
        const int buf = tw & 1;
        if (tw < NT - 1) {
            STSW(buf ^ 1);            // fill other buffer (overlaps MMA below)
            if (tw < NT - 2) LOADW(tw + 2);
        }
        const unsigned abufo = buf ? ABUF : 0u;
        const unsigned xbufo = buf ? XBUF : 0u;
        #pragma unroll
        for (int kb = 0; kb < 2; kb++) {
            unsigned ah[2][4], al[2][4];
            #pragma unroll
            for (int mt = 0; mt < 2; mt++) {
                const unsigned off = aoff + (unsigned)((mt * 16 * AS_STR + kb * 8) * 4);
                ldsm_x4(ah[mt], ash_u32 + abufo + off);
                ldsm_x4(al[mt], asl_u32 + abufo + off);
            }
            unsigned bh[8], bl[8];
            ldsm_x4(bh,     xth_u32 + xbufo + xbase + kb * 32);
            ldsm_x4(bh + 4, xth_u32 + xbufo + xbase + 16 * XT_STR * 4 + kb * 32);
            ldsm_x4(bl,     xtl_u32 + xbufo + xbase + kb * 32);
            ldsm_x4(bl + 4, xtl_u32 + xbufo + xbase + 16 * XT_STR * 4 + kb * 32);
            #pragma unroll
            for (int nt = 0; nt < 4; nt++) {
                unsigned bh0 = bh[2 * nt], bh1 = bh[2 * nt + 1];
                unsigned bl0 = bl[2 * nt], bl1 = bl[2 * nt + 1];
                #pragma unroll
                for (int mt = 0; mt < 2; mt++) {
                    mma_bf16(acc[mt][nt], ah[mt], bh0, bh1);  // hh
                    mma_bf16(acc[mt][nt], ah[mt], bl0, bl1);  // hl
                    mma_bf16(acc[mt][nt], al[mt], bh0, bh1);  // lh
                }
            }
        }
        __syncthreads();
    }

    // epilogue
    float* Cg = g_v + (size_t)bb * CH * VHW;
    #pragma unroll
    for (int mt = 0; mt < 2; mt++) {
        const int r0 = m0 + warp_m + mt * 16 + g;
        const float bv0 = bias[r0];
        const float bv1 = bias[r0 + 8];
        #pragma unroll
        for (int nt = 0; nt < 4; nt++) {
            const int c = n0 + warp_n + nt * 8 + 2 * t4;
            *(float2*)&Cg[(size_t)r0 * VHW + c] =
                make_float2(acc[mt][nt][0] + bv0, acc[mt][nt][1] + bv0);
            *(float2*)&Cg[(size_t)(r0 + 8) * VHW + c] =
                make_float2(acc[mt][nt][2] + bv1, acc[mt][nt][3] + bv1);
        }
    }
}

// ---------------------------------------------------------------------------
// Phase 1: fused bilinear + partial cossim over a 32-channel chunk.
// grid (8, 32, 8) = 2048 blocks (~14/SM), 128 thr; 128(w)x4(h), 4 px/thread.
// 8-deep register prefetch FIFO on x_cnn + __ldcs streaming.
// ---------------------------------------------------------------------------
#define CB_CCH   32
#define CB_ELEMS 102   // 3 rows * 34 cols
#define PF       8

__global__ __launch_bounds__(128)
void cossim_part_kernel(const float* __restrict__ xcnn) {
    const int cc   = blockIdx.x;
    const int by   = blockIdx.y;
    const int bb   = blockIdx.z;
    const int lane = threadIdx.x & 31;
    const int wrp  = threadIdx.x >> 5;
    const int y    = by * 4 + wrp;
    const int x0   = lane * 4;
    const int c0   = cc * CB_CCH;

    __shared__ float vsf[CB_CCH * CB_ELEMS];   // 12.8 KB

    int gsrc[4];
    #pragma unroll
    for (int e = 0; e < 4; e++) {
        int idx = lane + 32 * e;
        int yy = idx / 34;
        int xx = idx - yy * 34;
        int gy = min(max(by - 1 + yy, 0), 31);
        int gx = min(max(xx - 1, 0), 31);
        gsrc[e] = gy * 32 + gx;
    }
    const bool valid3 = (lane + 96) < CB_ELEMS;

    const float fy = (wrp == 0) ? 0.625f : (wrp == 1) ? 0.875f
                   : (wrp == 2) ? 0.125f : 0.375f;
    const int rb = (wrp >= 2) ? 34 : 0;

    const float* xc = xcnn + (size_t)(bb * CH + c0) * HWOUT + (size_t)y * W_OUT + x0;

    // start the x_cnn prefetch FIFO BEFORE staging (overlaps v gather)
    float4 xq[PF];
    #pragma unroll
    for (int i = 0; i < PF; i++)
        xq[i] = __ldcs((const float4*)(xc + (size_t)i * HWOUT));

    const float* vbase = g_v + (size_t)bb * CH * VHW;
    for (int c = wrp; c < CB_CCH; c += 4) {
        const float* vc = vbase + (size_t)(c0 + c) * VHW;
        float t0 = vc[gsrc[0]];
        float t1 = vc[gsrc[1]];
        float t2 = vc[gsrc[2]];
        float* d = &vsf[c * CB_ELEMS + lane];
        d[0] = t0; d[32] = t1; d[64] = t2;
        if (valid3) d[96] = vc[gsrc[3]];
    }
    __syncthreads();

    float dot0=0.f,dot1=0.f,dot2=0.f,dot3=0.f;
    float sc0=0.f,sc1=0.f,sc2=0.f,sc3=0.f;
    float sv0=0.f,sv1=0.f,sv2=0.f,sv3=0.f;

    #pragma unroll 8
    for (int c = 0; c < CB_CCH; c++) {
        float4 x4 = xq[c & (PF - 1)];
        if (c + PF < CB_CCH)
            xq[c & (PF - 1)] = __ldcs((const float4*)(xc + (size_t)(c + PF) * HWOUT));
        const float* v0 = &vsf[c * CB_ELEMS + rb + lane];
        float a0 = v0[0],  a1 = v0[1],  a2 = v0[2];
        float b0 = v0[34], b1 = v0[35], b2 = v0[36];
        float cv0 = fmaf(fy, b0 - a0, a0);
        float cv1 = fmaf(fy, b1 - a1, a1);
        float cv2 = fmaf(fy, b2 - a2, a2);
        float d01 = cv1 - cv0, d12 = cv2 - cv1;
        float vu0 = fmaf(0.625f, d01, cv0);
        float vu1 = fmaf(0.875f, d01, cv0);
        float vu2 = fmaf(0.125f, d12, cv1);
        float vu3 = fmaf(0.375f, d12, cv1);
        dot0 = fmaf(x4.x, vu0, dot0); sc0 = fmaf(x4.x, x4.x, sc0); sv0 = fmaf(vu0, vu0, sv0);
        dot1 = fmaf(x4.y, vu1, dot1); sc1 = fmaf(x4.y, x4.y, sc1); sv1 = fmaf(vu1, vu1, sv1);
        dot2 = fmaf(x4.z, vu2, dot2); sc2 = fmaf(x4.z, x4.z, sc2); sv2 = fmaf(vu2, vu2, sv2);
        dot3 = fmaf(x4.w, vu3, dot3); sc3 = fmaf(x4.w, x4.w, sc3); sv3 = fmaf(vu3, vu3, sv3);
    }

    const size_t pix = (size_t)y * W_OUT + x0;
    float* p = g_part + ((size_t)(cc * BATCH + bb)) * HWOUT + pix;
    const size_t sstr = (size_t)NCHUNK * BATCH * HWOUT;
    *(float4*)(p)            = make_float4(dot0, dot1, dot2, dot3);
    *(float4*)(p + sstr)     = make_float4(sc0, sc1, sc2, sc3);
    *(float4*)(p + 2 * sstr) = make_float4(sv0, sv1, sv2, sv3);
}

// ---------------------------------------------------------------------------
// Phase 2: reduce 8 chunk-partials -> cosine similarity.
// 4 px/thread, 64-thread blocks -> 512 blocks.
// ---------------------------------------------------------------------------
__global__ __launch_bounds__(64)
void cossim_reduce_kernel(float* __restrict__ out) {
    const int gid = blockIdx.x * 64 + threadIdx.x;
    const size_t pix4 = (size_t)gid * 4;
    const int bb  = (int)(pix4 >> 14);
    const size_t pix = pix4 & (HWOUT - 1);
    const size_t sstr = (size_t)NCHUNK * BATCH * HWOUT;
    const float* p = g_part + (size_t)bb * HWOUT + pix;
    const size_t cstr = (size_t)BATCH * HWOUT;

    float4 dot = make_float4(0.f, 0.f, 0.f, 0.f);
    float4 sc  = dot, sv = dot;
    #pragma unroll
    for (int cc = 0; cc < NCHUNK; cc++) {
        float4 d = *(const float4*)(p + cc * cstr);
        float4 a = *(const float4*)(p + cc * cstr + sstr);
        float4 b = *(const float4*)(p + cc * cstr + 2 * sstr);
        dot.x += d.x; dot.y += d.y; dot.z += d.z; dot.w += d.w;
        sc.x  += a.x; sc.y  += a.y; sc.z  += a.z; sc.w  += a.w;
        sv.x  += b.x; sv.y  += b.y; sv.z  += b.z; sv.w  += b.w;
    }
    float4 o;
    o.x = dot.x / (sqrtf(sc.x) * sqrtf(sv.x) + 1e-8f);
    o.y = dot.y / (sqrtf(sc.y) * sqrtf(sv.y) + 1e-8f);
    o.z = dot.z / (sqrtf(sc.z) * sqrtf(sv.z) + 1e-8f);
    o.w = dot.w / (sqrtf(sc.w) * sqrtf(sv.w) + 1e-8f);
    *(float4*)&out[pix4] = o;
}

// ---------------------------------------------------------------------------
extern "C" void kernel_launch(void* const* d_in, const int* in_sizes, int n_in,
                              void* d_out, int out_size) {
    const float* x_cnn = (const float*)d_in[0];   // [8,256,128,128]
    const float* x_vit = (const float*)d_in[1];   // [8,512,32,32]
    const float* Wmat  = (const float*)d_in[2];   // [256,512]
    const float* bias  = (const float*)d_in[3];   // [256]
    float* out = (float*)d_out;                   // [8,1,128,128]

    gemm_fused_kernel<<<dim3(VHW / 64, CH / 128, BATCH), 256>>>(x_vit, Wmat, bias);
    cossim_part_kernel<<<dim3(NCHUNK, H_OUT / 4, BATCH), 128>>>(x_cnn);
    cossim_reduce_kernel<<<dim3(BATCH * HWOUT / 4 / 64), 64>>>(out);
}

// round 17
// speedup vs baseline: 1.4844x; 1.0565x over previous
#include <cuda_runtime.h>
#include <cuda_bf16.h>
#include <cstdint>

#define BATCH 8
#define CH    256
#define KDIM  512
#define KP    256      // KDIM/2 packed bf16 pairs
#define VHW   1024     // 32*32
#define H_OUT 128
#define W_OUT 128
#define HWOUT (H_OUT * W_OUT)

// v scratch (8 MiB, L2-resident between kernels)
__device__ float g_v[BATCH * CH * VHW];
// cossim partials: [s(3)][chunk(8)][b(8)][pix] = 12.6 MB
#define NCHUNK 8
__device__ float g_part[3 * NCHUNK * BATCH * HWOUT];

// ---------------------------------------------------------------------------
// bf16 split + mma helpers
// ---------------------------------------------------------------------------
__device__ __forceinline__ void pack2(float a, float b, unsigned& hi, unsigned& lo) {
    __nv_bfloat16 ha = __float2bfloat16(a);
    __nv_bfloat16 hb = __float2bfloat16(b);
    __nv_bfloat16 la = __float2bfloat16(a - __bfloat162float(ha));
    __nv_bfloat16 lb = __float2bfloat16(b - __bfloat162float(hb));
    hi = (unsigned)__bfloat16_as_ushort(ha) | ((unsigned)__bfloat16_as_ushort(hb) << 16);
    lo = (unsigned)__bfloat16_as_ushort(la) | ((unsigned)__bfloat16_as_ushort(lb) << 16);
}

__device__ __forceinline__ void mma_bf16(float* d, const unsigned* a, unsigned b0, unsigned b1) {
    asm volatile(
        "mma.sync.aligned.m16n8k16.row.col.f32.bf16.bf16.f32 "
        "{%0,%1,%2,%3}, {%4,%5,%6,%7}, {%8,%9}, {%0,%1,%2,%3};"
        : "+f"(d[0]), "+f"(d[1]), "+f"(d[2]), "+f"(d[3])
        : "r"(a[0]), "r"(a[1]), "r"(a[2]), "r"(a[3]), "r"(b0), "r"(b1));
}

__device__ __forceinline__ void ldsm_x4(unsigned* r, unsigned saddr) {
    asm volatile(
        "ldmatrix.sync.aligned.m8n8.x4.shared.b16 {%0,%1,%2,%3}, [%4];"
        : "=r"(r[0]), "=r"(r[1]), "=r"(r[2]), "=r"(r[3]) : "r"(saddr));
}

// ---------------------------------------------------------------------------
// Fused convert + tensor-core GEMM (R14-validated, 31.4us):
// C[256,1024] = W @ X + bias per batch; bf16-split (hh + hl + lh),
// fp32 reg-prefetch -> split -> STS. BM=128, BN=64, 256 thr,
// 8 warps = 4m x 2n (32x32 warp tiles), grid 256.
// X stored transposed [n][kp]; BOTH operands' fragments via ldmatrix.x4.
// ---------------------------------------------------------------------------
#define AS_STR 20     // ldsm rows: (m*20)%32 in {0,20,8,28,16,4,24,12} -> disjoint 16B groups
#define XT_STR 20     // same conflict-free pattern for X rows (n-major)

__global__ __launch_bounds__(256)
void gemm_fused_kernel(const float* __restrict__ xvit,
                       const float* __restrict__ Wmat,
                       const float* __restrict__ bias) {
    const int n0 = blockIdx.x * 64;
    const int m0 = blockIdx.y * 128;
    const int bb = blockIdx.z;

    __shared__ unsigned Ash[128 * AS_STR];
    __shared__ unsigned Asl[128 * AS_STR];
    __shared__ unsigned Xth[64 * XT_STR];   // [n][kp window 16]
    __shared__ unsigned Xtl[64 * XT_STR];

    const int tid  = threadIdx.x;
    const int wid  = tid >> 5;
    const int lane = tid & 31;
    const int g    = lane >> 2;
    const int t4   = lane & 3;
    const int warp_m = (wid >> 1) * 32;   // 0/32/64/96
    const int warp_n = (wid & 1) * 32;    // 0/32

    // ldmatrix lane-address components (A)
    const int lrow = (lane & 7) + ((lane >> 3) & 1) * 8;   // 0..15
    const int lcol = (lane >> 4) * 4;                      // 0 or 4
    const unsigned ash_u32 = (unsigned)__cvta_generic_to_shared(Ash);
    const unsigned asl_u32 = (unsigned)__cvta_generic_to_shared(Asl);
    // ldmatrix lane-address components (B): matrix j=(lane>>3) = (nt-half, b0/b1)
    const int bj = lane >> 3;
    const int br = lane & 7;
    const unsigned xth_u32 = (unsigned)__cvta_generic_to_shared(Xth);
    const unsigned xtl_u32 = (unsigned)__cvta_generic_to_shared(Xtl);
    const unsigned xbase =
        (unsigned)(((warp_n + (bj >> 1) * 8 + br) * XT_STR + (bj & 1) * 4) * 4);

    // staging indices
    const int arow = tid >> 1, ahalf = tid & 1;   // A: 128 rows x 2 k-halves(16)
    const int xn   = tid & 63;                    // X: n column 0..63
    const int kpb  = tid >> 6;                    // X: kp block 0..3 (4 kp = 8 k)

    const float* wp = Wmat + (size_t)(m0 + arow) * KDIM + ahalf * 16;
    const float* xp = xvit + ((size_t)bb * KDIM + kpb * 8) * VHW + n0 + xn;

    float4 wa[4];   // 16 k of W
    float  xv[8];   // 8 k rows of one n column

    #pragma unroll
    for (int q = 0; q < 4; q++) wa[q] = *(const float4*)(wp + 4 * q);
    #pragma unroll
    for (int j = 0; j < 8; j++) xv[j] = xp[(size_t)j * VHW];

    float acc[2][4][4];
    #pragma unroll
    for (int i = 0; i < 2; i++)
        #pragma unroll
        for (int j = 0; j < 4; j++)
            #pragma unroll
            for (int q = 0; q < 4; q++) acc[i][j][q] = 0.f;

    const int NT = KP / 16;   // 16 windows of 32 k
    for (int tw = 0; tw < NT; tw++) {
        {   // A: split + STS
            uint4 h0, l0, h1, l1;
            pack2(wa[0].x, wa[0].y, h0.x, l0.x);
            pack2(wa[0].z, wa[0].w, h0.y, l0.y);
            pack2(wa[1].x, wa[1].y, h0.z, l0.z);
            pack2(wa[1].z, wa[1].w, h0.w, l0.w);
            pack2(wa[2].x, wa[2].y, h1.x, l1.x);
            pack2(wa[2].z, wa[2].w, h1.y, l1.y);
            pack2(wa[3].x, wa[3].y, h1.z, l1.z);
            pack2(wa[3].z, wa[3].w, h1.w, l1.w);
            unsigned* dh = &Ash[arow * AS_STR + ahalf * 8];
            unsigned* dl = &Asl[arow * AS_STR + ahalf * 8];
            *(uint4*)dh = h0; *(uint4*)(dh + 4) = h1;
            *(uint4*)dl = l0; *(uint4*)(dl + 4) = l1;
        }
        {   // X: split + STS transposed (one n, 4 kp words)
            uint4 h, l;
            pack2(xv[0], xv[1], h.x, l.x);
            pack2(xv[2], xv[3], h.y, l.y);
            pack2(xv[4], xv[5], h.z, l.z);
            pack2(xv[6], xv[7], h.w, l.w);
            *(uint4*)&Xth[xn * XT_STR + kpb * 4] = h;
            *(uint4*)&Xtl[xn * XT_STR + kpb * 4] = l;
        }
        __syncthreads();

        if (tw < NT - 1) {   // prefetch next window (overlaps MMA)
            const float* wpn = wp + (tw + 1) * 32;
            const float* xpn = xp + (size_t)((tw + 1) * 32) * VHW;
            #pragma unroll
            for (int q = 0; q < 4; q++) wa[q] = *(const float4*)(wpn + 4 * q);
            #pragma unroll
            for (int j = 0; j < 8; j++) xv[j] = xpn[(size_t)j * VHW];
        }

        #pragma unroll
        for (int kb = 0; kb < 2; kb++) {
            unsigned ah[2][4], al[2][4];
            #pragma unroll
            for (int mt = 0; mt < 2; mt++) {
                const unsigned off =
                    (unsigned)(((warp_m + mt * 16 + lrow) * AS_STR + kb * 8 + lcol) * 4);
                ldsm_x4(ah[mt], ash_u32 + off);
                ldsm_x4(al[mt], asl_u32 + off);
            }
            unsigned bh[8], bl[8];
            ldsm_x4(bh,     xth_u32 + xbase + kb * 32);
            ldsm_x4(bh + 4, xth_u32 + xbase + 16 * XT_STR * 4 + kb * 32);
            ldsm_x4(bl,     xtl_u32 + xbase + kb * 32);
            ldsm_x4(bl + 4, xtl_u32 + xbase + 16 * XT_STR * 4 + kb * 32);
            #pragma unroll
            for (int nt = 0; nt < 4; nt++) {
                unsigned bh0 = bh[2 * nt], bh1 = bh[2 * nt + 1];
                unsigned bl0 = bl[2 * nt], bl1 = bl[2 * nt + 1];
                #pragma unroll
                for (int mt = 0; mt < 2; mt++) {
                    mma_bf16(acc[mt][nt], ah[mt], bh0, bh1);  // hh
                    mma_bf16(acc[mt][nt], ah[mt], bl0, bl1);  // hl
                    mma_bf16(acc[mt][nt], al[mt], bh0, bh1);  // lh
                }
            }
        }
        __syncthreads();
    }

    // epilogue
    float* Cg = g_v + (size_t)bb * CH * VHW;
    #pragma unroll
    for (int mt = 0; mt < 2; mt++) {
        const int r0 = m0 + warp_m + mt * 16 + g;
        const float bv0 = bias[r0];
        const float bv1 = bias[r0 + 8];
        #pragma unroll
        for (int nt = 0; nt < 4; nt++) {
            const int c = n0 + warp_n + nt * 8 + 2 * t4;
            *(float2*)&Cg[(size_t)r0 * VHW + c] =
                make_float2(acc[mt][nt][0] + bv0, acc[mt][nt][1] + bv0);
            *(float2*)&Cg[(size_t)(r0 + 8) * VHW + c] =
                make_float2(acc[mt][nt][2] + bv1, acc[mt][nt][3] + bv1);
        }
    }
}

// ---------------------------------------------------------------------------
// Phase 1: fused bilinear + partial cossim over a 32-channel chunk.
// grid (8, 32, 8) = 2048 blocks (~14/SM), 128 thr; 128(w)x4(h), 4 px/thread.
// 8-deep register prefetch FIFO on x_cnn + __ldcs streaming. (R15-validated.)
// ---------------------------------------------------------------------------
#define CB_CCH   32
#define CB_ELEMS 102   // 3 rows * 34 cols
#define PF       8

__global__ __launch_bounds__(128)
void cossim_part_kernel(const float* __restrict__ xcnn) {
    const int cc   = blockIdx.x;
    const int by   = blockIdx.y;
    const int bb   = blockIdx.z;
    const int lane = threadIdx.x & 31;
    const int wrp  = threadIdx.x >> 5;
    const int y    = by * 4 + wrp;
    const int x0   = lane * 4;
    const int c0   = cc * CB_CCH;

    __shared__ float vsf[CB_CCH * CB_ELEMS];   // 12.8 KB

    int gsrc[4];
    #pragma unroll
    for (int e = 0; e < 4; e++) {
        int idx = lane + 32 * e;
        int yy = idx / 34;
        int xx = idx - yy * 34;
        int gy = min(max(by - 1 + yy, 0), 31);
        int gx = min(max(xx - 1, 0), 31);
        gsrc[e] = gy * 32 + gx;
    }
    const bool valid3 = (lane + 96) < CB_ELEMS;

    const float fy = (wrp == 0) ? 0.625f : (wrp == 1) ? 0.875f
                   : (wrp == 2) ? 0.125f : 0.375f;
    const int rb = (wrp >= 2) ? 34 : 0;

    const float* xc = xcnn + (size_t)(bb * CH + c0) * HWOUT + (size_t)y * W_OUT + x0;

    // start the x_cnn prefetch FIFO BEFORE staging (overlaps v gather)
    float4 xq[PF];
    #pragma unroll
    for (int i = 0; i < PF; i++)
        xq[i] = __ldcs((const float4*)(xc + (size_t)i * HWOUT));

    const float* vbase = g_v + (size_t)bb * CH * VHW;
    for (int c = wrp; c < CB_CCH; c += 4) {
        const float* vc = vbase + (size_t)(c0 + c) * VHW;
        float t0 = vc[gsrc[0]];
        float t1 = vc[gsrc[1]];
        float t2 = vc[gsrc[2]];
        float* d = &vsf[c * CB_ELEMS + lane];
        d[0] = t0; d[32] = t1; d[64] = t2;
        if (valid3) d[96] = vc[gsrc[3]];
    }
    __syncthreads();

    float dot0=0.f,dot1=0.f,dot2=0.f,dot3=0.f;
    float sc0=0.f,sc1=0.f,sc2=0.f,sc3=0.f;
    float sv0=0.f,sv1=0.f,sv2=0.f,sv3=0.f;

    #pragma unroll 8
    for (int c = 0; c < CB_CCH; c++) {
        float4 x4 = xq[c & (PF - 1)];
        if (c + PF < CB_CCH)
            xq[c & (PF - 1)] = __ldcs((const float4*)(xc + (size_t)(c + PF) * HWOUT));
        const float* v0 = &vsf[c * CB_ELEMS + rb + lane];
        float a0 = v0[0],  a1 = v0[1],  a2 = v0[2];
        float b0 = v0[34], b1 = v0[35], b2 = v0[36];
        float cv0 = fmaf(fy, b0 - a0, a0);
        float cv1 = fmaf(fy, b1 - a1, a1);
        float cv2 = fmaf(fy, b2 - a2, a2);
        float d01 = cv1 - cv0, d12 = cv2 - cv1;
        float vu0 = fmaf(0.625f, d01, cv0);
        float vu1 = fmaf(0.875f, d01, cv0);
        float vu2 = fmaf(0.125f, d12, cv1);
        float vu3 = fmaf(0.375f, d12, cv1);
        dot0 = fmaf(x4.x, vu0, dot0); sc0 = fmaf(x4.x, x4.x, sc0); sv0 = fmaf(vu0, vu0, sv0);
        dot1 = fmaf(x4.y, vu1, dot1); sc1 = fmaf(x4.y, x4.y, sc1); sv1 = fmaf(vu1, vu1, sv1);
        dot2 = fmaf(x4.z, vu2, dot2); sc2 = fmaf(x4.z, x4.z, sc2); sv2 = fmaf(vu2, vu2, sv2);
        dot3 = fmaf(x4.w, vu3, dot3); sc3 = fmaf(x4.w, x4.w, sc3); sv3 = fmaf(vu3, vu3, sv3);
    }

    const size_t pix = (size_t)y * W_OUT + x0;
    float* p = g_part + ((size_t)(cc * BATCH + bb)) * HWOUT + pix;
    const size_t sstr = (size_t)NCHUNK * BATCH * HWOUT;
    *(float4*)(p)            = make_float4(dot0, dot1, dot2, dot3);
    *(float4*)(p + sstr)     = make_float4(sc0, sc1, sc2, sc3);
    *(float4*)(p + 2 * sstr) = make_float4(sv0, sv1, sv2, sv3);
}

// ---------------------------------------------------------------------------
// Phase 2: reduce 8 chunk-partials -> cosine similarity.
// 4 px/thread, 64-thread blocks -> 512 blocks. Loads front-batched
// (6 independent LDG.128 per chunk pair) to raise MLP.
// ---------------------------------------------------------------------------
__global__ __launch_bounds__(64)
void cossim_reduce_kernel(float* __restrict__ out) {
    const int gid = blockIdx.x * 64 + threadIdx.x;
    const size_t pix4 = (size_t)gid * 4;
    const int bb  = (int)(pix4 >> 14);
    const size_t pix = pix4 & (HWOUT - 1);
    const size_t sstr = (size_t)NCHUNK * BATCH * HWOUT;
    const float* p = g_part + (size_t)bb * HWOUT + pix;
    const size_t cstr = (size_t)BATCH * HWOUT;

    float4 d[NCHUNK], a[NCHUNK], b[NCHUNK];
    #pragma unroll
    for (int cc = 0; cc < NCHUNK; cc++) {
        d[cc] = *(const float4*)(p + cc * cstr);
        a[cc] = *(const float4*)(p + cc * cstr + sstr);
        b[cc] = *(const float4*)(p + cc * cstr + 2 * sstr);
    }
    float4 dot = make_float4(0.f, 0.f, 0.f, 0.f);
    float4 sc  = dot, sv = dot;
    #pragma unroll
    for (int cc = 0; cc < NCHUNK; cc++) {
        dot.x += d[cc].x; dot.y += d[cc].y; dot.z += d[cc].z; dot.w += d[cc].w;
        sc.x  += a[cc].x; sc.y  += a[cc].y; sc.z  += a[cc].z; sc.w  += a[cc].w;
        sv.x  += b[cc].x; sv.y  += b[cc].y; sv.z  += b[cc].z; sv.w  += b[cc].w;
    }
    float4 o;
    o.x = dot.x / (sqrtf(sc.x) * sqrtf(sv.x) + 1e-8f);
    o.y = dot.y / (sqrtf(sc.y) * sqrtf(sv.y) + 1e-8f);
    o.z = dot.z / (sqrtf(sc.z) * sqrtf(sv.z) + 1e-8f);
    o.w = dot.w / (sqrtf(sc.w) * sqrtf(sv.w) + 1e-8f);
    *(float4*)&out[pix4] = o;
}

// ---------------------------------------------------------------------------
extern "C" void kernel_launch(void* const* d_in, const int* in_sizes, int n_in,
                              void* d_out, int out_size) {
    const float* x_cnn = (const float*)d_in[0];   // [8,256,128,128]
    const float* x_vit = (const float*)d_in[1];   // [8,512,32,32]
    const float* Wmat  = (const float*)d_in[2];   // [256,512]
    const float* bias  = (const float*)d_in[3];   // [256]
    float* out = (float*)d_out;                   // [8,1,128,128]

    gemm_fused_kernel<<<dim3(VHW / 64, CH / 128, BATCH), 256>>>(x_vit, Wmat, bias);
    cossim_part_kernel<<<dim3(NCHUNK, H_OUT / 4, BATCH), 128>>>(x_cnn);
    cossim_reduce_kernel<<<dim3(BATCH * HWOUT / 4 / 64), 64>>>(out);
}